// round 3
// baseline (speedup 1.0000x reference)
#include <cuda_runtime.h>
#include <mma.h>
#include <cstdint>
#include <math.h>

using namespace nvcuda;

// ---------------------------------------------------------------------------
// Problem: 8-expert FFN, fp32. Per expert: [2048x2048]@[2048x8192] -> GELU
// -> @[8192x2048]. Total 1.1 TFLOP.
// NOTE: harness compiles for compute_103 (no 'a') -> tcgen05/TMA unavailable.
// Use portable tf32 WMMA (HMMA fallback path) with explicit RNA rounding.
// ---------------------------------------------------------------------------
#define EXP_E 8
#define EXP_C 2048
#define EXP_D 2048
#define EXP_F 8192

// Intermediate H = gelu(X@W1+b1): [E, C, F] fp32 scratch (512 MB device global)
__device__ __align__(256) float g_H[(size_t)EXP_E * EXP_C * EXP_F];

// ---------------------------------------------------------------------------
// Tiling
// ---------------------------------------------------------------------------
#define BM 128
#define BN 128
#define BK 16
#define STAGES 4
#define A_STRIDE 20                        // 16 + 4 pad (floats)
#define B_STRIDE 132                       // 128 + 4 pad (floats)
#define A_FLOATS (BM * A_STRIDE)           // 2560
#define B_FLOATS (BK * B_STRIDE)           // 2112
#define STAGE_FLOATS (A_FLOATS + B_FLOATS) // 4672
#define SMEM_BYTES (STAGES * STAGE_FLOATS * 4)   // 74752

// ---------------------------------------------------------------------------
// cp.async helpers (compute_80+ portable)
// ---------------------------------------------------------------------------
__device__ __forceinline__ uint32_t smem_u32(const void* p) {
    uint32_t a;
    asm("{ .reg .u64 t; cvta.to.shared.u64 t, %1; cvt.u32.u64 %0, t; }"
        : "=r"(a) : "l"(p));
    return a;
}

#define CP_ASYNC_CG(dst_u32, src_ptr) \
    asm volatile("cp.async.cg.shared.global [%0], [%1], 16;" \
                 :: "r"(dst_u32), "l"(src_ptr) : "memory")
#define CP_ASYNC_COMMIT() asm volatile("cp.async.commit_group;" ::: "memory")
#define CP_ASYNC_WAIT(n)  asm volatile("cp.async.wait_group %0;" :: "n"(n) : "memory")

__device__ __forceinline__ float gelu_tanh(float x) {
    float u = 0.7978845608028654f * fmaf(0.044715f * x, x * x, x);
    return 0.5f * x * (1.0f + tanhf(u));
}

// ---------------------------------------------------------------------------
// Batched GEMM: Out[e][m][n] = epi( sum_k A[e][m][k]*B[e][k][n] + bias[e][n] )
//   A: [E, 2048, K] row-major    B: [E, K, ldN] row-major
//   grid = (2048/BM, ldN/BN, E), 256 threads, 2 CTAs/SM
// ---------------------------------------------------------------------------
template <bool GELU>
__global__ void __launch_bounds__(256, 2)
moe_gemm_tf32(const float* __restrict__ A, const float* __restrict__ B,
              const float* __restrict__ bias, float* __restrict__ Out,
              int K, int ldN)
{
    extern __shared__ float smem[];
    const int tid  = threadIdx.x;
    const int warp = tid >> 5;
    const int lane = tid & 31;
    const int e  = blockIdx.z;
    const int m0 = blockIdx.x * BM;
    const int n0 = blockIdx.y * BN;
    const int KT = K / BK;

    const float* Ae = A    + (size_t)e * EXP_C * K;
    const float* Be = B    + (size_t)e * K * ldN;
    const float* be = bias + (size_t)e * ldN;
    float*       Oe = Out  + (size_t)e * EXP_C * ldN;

    // warp grid: 4 (M) x 2 (N); warp tile 32x64 = 2x4 wmma 16x16 tiles
    const int wm = warp >> 1;   // 0..3
    const int wn = warp & 1;    // 0..1

    // per-thread cp.async coordinates
    const int arow   = tid >> 2;        // 0..63  (A rows; +64 second rep)
    const int achunk = tid & 3;         // 4 x float4 per 16-float row
    const int brow   = tid >> 5;        // 0..7   (B k-rows; +8 second rep)
    const int bchunk = tid & 31;        // 32 x float4 per 128-float row

    const float* a_src0 = Ae + (size_t)(m0 + arow) * K + achunk * 4;
    const float* b_src0 = Be + (size_t)brow * ldN + n0 + bchunk * 4;

    wmma::fragment<wmma::accumulator, 16, 16, 8, float> acc[2][4];
#pragma unroll
    for (int mt = 0; mt < 2; ++mt)
#pragma unroll
        for (int nt = 0; nt < 4; ++nt)
            wmma::fill_fragment(acc[mt][nt], 0.0f);

    auto issue_tile = [&](int t) {
        const int s = t & (STAGES - 1);
        float* sA = smem + s * STAGE_FLOATS;
        float* sB = sA + A_FLOATS;
        const int k0 = t * BK;
        // A: 128 rows x 16 floats
        const float* asrc = a_src0 + k0;
        uint32_t adst = smem_u32(sA + arow * A_STRIDE + achunk * 4);
        CP_ASYNC_CG(adst, asrc);
        CP_ASYNC_CG(adst + 64 * A_STRIDE * 4, asrc + (size_t)64 * K);
        // B: 16 k-rows x 128 floats
        const float* bsrc = b_src0 + (size_t)k0 * ldN;
        uint32_t bdst = smem_u32(sB + brow * B_STRIDE + bchunk * 4);
        CP_ASYNC_CG(bdst, bsrc);
        CP_ASYNC_CG(bdst + 8 * B_STRIDE * 4, bsrc + (size_t)8 * ldN);
    };

    // prefetch STAGES-1 tiles
#pragma unroll
    for (int t = 0; t < STAGES - 1; ++t) {
        issue_tile(t);
        CP_ASYNC_COMMIT();
    }

    for (int t = 0; t < KT; ++t) {
        if (t + STAGES - 1 < KT) issue_tile(t + STAGES - 1);
        CP_ASYNC_COMMIT();                    // unconditional: keeps group count uniform
        CP_ASYNC_WAIT(STAGES - 2);            // tile t resident
        __syncthreads();

        const int s = t & (STAGES - 1);
        const float* sA = smem + s * STAGE_FLOATS;
        const float* sB = sA + A_FLOATS;

#pragma unroll
        for (int kk = 0; kk < 2; ++kk) {      // two k=8 steps per BK=16
            wmma::fragment<wmma::matrix_a, 16, 16, 8,
                           wmma::precision::tf32, wmma::row_major> af[2];
            wmma::fragment<wmma::matrix_b, 16, 16, 8,
                           wmma::precision::tf32, wmma::row_major> bf[4];
#pragma unroll
            for (int mt = 0; mt < 2; ++mt) {
                wmma::load_matrix_sync(
                    af[mt], sA + (wm * 32 + mt * 16) * A_STRIDE + kk * 8, A_STRIDE);
#pragma unroll
                for (int i = 0; i < af[mt].num_elements; ++i)
                    af[mt].x[i] = wmma::__float_to_tf32(af[mt].x[i]);  // RNA round
            }
#pragma unroll
            for (int nt = 0; nt < 4; ++nt) {
                wmma::load_matrix_sync(
                    bf[nt], sB + kk * 8 * B_STRIDE + wn * 64 + nt * 16, B_STRIDE);
#pragma unroll
                for (int i = 0; i < bf[nt].num_elements; ++i)
                    bf[nt].x[i] = wmma::__float_to_tf32(bf[nt].x[i]);
            }
#pragma unroll
            for (int mt = 0; mt < 2; ++mt)
#pragma unroll
                for (int nt = 0; nt < 4; ++nt)
                    wmma::mma_sync(acc[mt][nt], af[mt], bf[nt], acc[mt][nt]);
        }
        __syncthreads();   // slot consumed before next overwrite
    }

    // ---- epilogue: stage each 16x16 accum tile through smem, fuse bias(+GELU)
    __syncthreads();
    float* patch = smem + warp * 16 * 20;     // per-warp 16x20 patch (reuses stage 0)
    const int prow = lane >> 1;
    const int pcol = (lane & 1) * 8;
#pragma unroll
    for (int mt = 0; mt < 2; ++mt) {
#pragma unroll
        for (int nt = 0; nt < 4; ++nt) {
            wmma::store_matrix_sync(patch, acc[mt][nt], 20, wmma::mem_row_major);
            __syncwarp();
            const int gm = m0 + wm * 32 + mt * 16 + prow;
            const int gn = n0 + wn * 64 + nt * 16 + pcol;
            float* op = Oe + (size_t)gm * ldN + gn;
            float f[8];
#pragma unroll
            for (int j = 0; j < 8; ++j) {
                float x = patch[prow * 20 + pcol + j] + __ldg(be + gn + j);
                f[j] = GELU ? gelu_tanh(x) : x;
            }
            *reinterpret_cast<float4*>(op)     = make_float4(f[0], f[1], f[2], f[3]);
            *reinterpret_cast<float4*>(op + 4) = make_float4(f[4], f[5], f[6], f[7]);
            __syncwarp();
        }
    }
}

// ---------------------------------------------------------------------------
// kernel_launch: GEMM1 (GELU -> g_H), then GEMM2 (-> d_out)
// ---------------------------------------------------------------------------
extern "C" void kernel_launch(void* const* d_in, const int* in_sizes, int n_in,
                              void* d_out, int out_size) {
    (void)in_sizes; (void)n_in; (void)out_size;
    const float* inputs = (const float*)d_in[0];
    const float* w1     = (const float*)d_in[1];
    const float* b1     = (const float*)d_in[2];
    const float* w2     = (const float*)d_in[3];
    const float* b2     = (const float*)d_in[4];
    float* out = (float*)d_out;

    void* hptr = nullptr;
    cudaGetSymbolAddress(&hptr, g_H);
    float* H = (float*)hptr;

    cudaFuncSetAttribute(moe_gemm_tf32<true>,
                         cudaFuncAttributeMaxDynamicSharedMemorySize, SMEM_BYTES);
    cudaFuncSetAttribute(moe_gemm_tf32<false>,
                         cudaFuncAttributeMaxDynamicSharedMemorySize, SMEM_BYTES);

    dim3 g1(EXP_C / BM, EXP_F / BN, EXP_E);   // (16, 64, 8)
    moe_gemm_tf32<true><<<g1, 256, SMEM_BYTES>>>(inputs, w1, b1, H, EXP_D, EXP_F);

    dim3 g2(EXP_C / BM, EXP_D / BN, EXP_E);   // (16, 16, 8)
    moe_gemm_tf32<false><<<g2, 256, SMEM_BYTES>>>(H, w2, b2, out, EXP_F, EXP_D);
}

// round 4
// speedup vs baseline: 1.0080x; 1.0080x over previous
#include <cuda_runtime.h>
#include <mma.h>
#include <cstdint>
#include <math.h>

using namespace nvcuda;

// ---------------------------------------------------------------------------
// Problem: 8-expert FFN, fp32. Per expert: [2048x2048]@[2048x8192] -> GELU
// -> @[8192x2048]. Total 1.1 TFLOP.
// Harness compiles compute_103 (no 'a') -> tcgen05/TMA unavailable; use the
// portable tf32 mma path (HMMA.1688). R4 change: all tf32 round-to-nearest
// moved to one-shot pre-pass kernels; GEMM inner loop has ZERO conversions.
// ---------------------------------------------------------------------------
#define EXP_E 8
#define EXP_C 2048
#define EXP_D 2048
#define EXP_F 8192

// Scratch (device globals; allocation-free at launch time):
__device__ __align__(256) float g_H  [(size_t)EXP_E * EXP_C * EXP_F];  // gelu(X@W1+b1), pre-rounded
__device__ __align__(256) float g_Xr [(size_t)EXP_E * EXP_C * EXP_D];  // rounded inputs
__device__ __align__(256) float g_W1r[(size_t)EXP_E * EXP_D * EXP_F];  // rounded w1
__device__ __align__(256) float g_W2r[(size_t)EXP_E * EXP_F * EXP_D];  // rounded w2

// ---------------------------------------------------------------------------
// Tiling
// ---------------------------------------------------------------------------
#define BM 128
#define BN 128
#define BK 16
#define STAGES 4
#define A_STRIDE 20                        // 16 + 4 pad (floats)
#define B_STRIDE 132                       // 128 + 4 pad (floats)
#define A_FLOATS (BM * A_STRIDE)           // 2560
#define B_FLOATS (BK * B_STRIDE)           // 2112
#define STAGE_FLOATS (A_FLOATS + B_FLOATS) // 4672
#define SMEM_BYTES (STAGES * STAGE_FLOATS * 4)   // 74752

// ---------------------------------------------------------------------------
// Helpers
// ---------------------------------------------------------------------------
__device__ __forceinline__ uint32_t smem_u32(const void* p) {
    uint32_t a;
    asm("{ .reg .u64 t; cvta.to.shared.u64 t, %1; cvt.u32.u64 %0, t; }"
        : "=r"(a) : "l"(p));
    return a;
}

#define CP_ASYNC_CG(dst_u32, src_ptr) \
    asm volatile("cp.async.cg.shared.global [%0], [%1], 16;" \
                 :: "r"(dst_u32), "l"(src_ptr) : "memory")
#define CP_ASYNC_COMMIT() asm volatile("cp.async.commit_group;" ::: "memory")
#define CP_ASYNC_WAIT(n)  asm volatile("cp.async.wait_group %0;" :: "n"(n) : "memory")

// Round-to-nearest fp32 -> tf32-in-fp32 (2 ALU ops). HW truncates tf32
// operands; RNA keeps the quantization bias incoherent (~4e-4 end-to-end).
__device__ __forceinline__ float rna_tf32(float f) {
    unsigned u = __float_as_uint(f);
    u = (u + 0x1000u) & 0xffffe000u;
    return __uint_as_float(u);
}

__device__ __forceinline__ float gelu_tanh(float x) {
    float u = 0.7978845608028654f * fmaf(0.044715f * x, x * x, x);
    return 0.5f * x * (1.0f + tanhf(u));
}

// One-shot elementwise RNA rounding pass (float4, grid-stride).
__global__ void __launch_bounds__(256)
round_tf32_pass(const float4* __restrict__ in, float4* __restrict__ out, size_t n4) {
    size_t i = (size_t)blockIdx.x * blockDim.x + threadIdx.x;
    size_t stride = (size_t)gridDim.x * blockDim.x;
    for (; i < n4; i += stride) {
        float4 v = in[i];
        v.x = rna_tf32(v.x); v.y = rna_tf32(v.y);
        v.z = rna_tf32(v.z); v.w = rna_tf32(v.w);
        out[i] = v;
    }
}

// ---------------------------------------------------------------------------
// Batched GEMM: Out[e][m][n] = epi( sum_k A[e][m][k]*B[e][k][n] + bias[e][n] )
//   A: [E, 2048, K] row-major (pre-rounded)   B: [E, K, ldN] row-major (pre-rounded)
//   grid = (2048/BM, ldN/BN, E), 256 threads, 2 CTAs/SM
//   GELU=true also RNA-rounds the output (it feeds GEMM2 as A).
// ---------------------------------------------------------------------------
template <bool GELU>
__global__ void __launch_bounds__(256, 2)
moe_gemm_tf32(const float* __restrict__ A, const float* __restrict__ B,
              const float* __restrict__ bias, float* __restrict__ Out,
              int K, int ldN)
{
    extern __shared__ float smem[];
    const int tid  = threadIdx.x;
    const int warp = tid >> 5;
    const int lane = tid & 31;
    const int e  = blockIdx.z;
    const int m0 = blockIdx.x * BM;
    const int n0 = blockIdx.y * BN;
    const int KT = K / BK;

    const float* Ae = A    + (size_t)e * EXP_C * K;
    const float* Be = B    + (size_t)e * K * ldN;
    const float* be = bias + (size_t)e * ldN;
    float*       Oe = Out  + (size_t)e * EXP_C * ldN;

    // warp grid: 4 (M) x 2 (N); warp tile 32x64 = 2x4 wmma 16x16 tiles
    const int wm = warp >> 1;   // 0..3
    const int wn = warp & 1;    // 0..1

    // per-thread cp.async coordinates
    const int arow   = tid >> 2;        // 0..63  (A rows; +64 second rep)
    const int achunk = tid & 3;         // 4 x float4 per 16-float row
    const int brow   = tid >> 5;        // 0..7   (B k-rows; +8 second rep)
    const int bchunk = tid & 31;        // 32 x float4 per 128-float row

    const float* a_src0 = Ae + (size_t)(m0 + arow) * K + achunk * 4;
    const float* b_src0 = Be + (size_t)brow * ldN + n0 + bchunk * 4;

    wmma::fragment<wmma::accumulator, 16, 16, 8, float> acc[2][4];
#pragma unroll
    for (int mt = 0; mt < 2; ++mt)
#pragma unroll
        for (int nt = 0; nt < 4; ++nt)
            wmma::fill_fragment(acc[mt][nt], 0.0f);

    auto issue_tile = [&](int t) {
        const int s = t & (STAGES - 1);
        float* sA = smem + s * STAGE_FLOATS;
        float* sB = sA + A_FLOATS;
        const int k0 = t * BK;
        // A: 128 rows x 16 floats
        const float* asrc = a_src0 + k0;
        uint32_t adst = smem_u32(sA + arow * A_STRIDE + achunk * 4);
        CP_ASYNC_CG(adst, asrc);
        CP_ASYNC_CG(adst + 64 * A_STRIDE * 4, asrc + (size_t)64 * K);
        // B: 16 k-rows x 128 floats
        const float* bsrc = b_src0 + (size_t)k0 * ldN;
        uint32_t bdst = smem_u32(sB + brow * B_STRIDE + bchunk * 4);
        CP_ASYNC_CG(bdst, bsrc);
        CP_ASYNC_CG(bdst + 8 * B_STRIDE * 4, bsrc + (size_t)8 * ldN);
    };

    // prefetch STAGES-1 tiles
#pragma unroll
    for (int t = 0; t < STAGES - 1; ++t) {
        issue_tile(t);
        CP_ASYNC_COMMIT();
    }

    for (int t = 0; t < KT; ++t) {
        if (t + STAGES - 1 < KT) issue_tile(t + STAGES - 1);
        CP_ASYNC_COMMIT();                    // unconditional: uniform group count
        CP_ASYNC_WAIT(STAGES - 2);            // tile t resident
        __syncthreads();

        const int s = t & (STAGES - 1);
        const float* sA = smem + s * STAGE_FLOATS;
        const float* sB = sA + A_FLOATS;

#pragma unroll
        for (int kk = 0; kk < 2; ++kk) {      // two k=8 steps per BK=16
            wmma::fragment<wmma::matrix_a, 16, 16, 8,
                           wmma::precision::tf32, wmma::row_major> af[2];
            wmma::fragment<wmma::matrix_b, 16, 16, 8,
                           wmma::precision::tf32, wmma::row_major> bf[4];
#pragma unroll
            for (int mt = 0; mt < 2; ++mt)
                wmma::load_matrix_sync(
                    af[mt], sA + (wm * 32 + mt * 16) * A_STRIDE + kk * 8, A_STRIDE);
#pragma unroll
            for (int nt = 0; nt < 4; ++nt)
                wmma::load_matrix_sync(
                    bf[nt], sB + kk * 8 * B_STRIDE + wn * 64 + nt * 16, B_STRIDE);
            // data pre-rounded: NO per-element conversion here
#pragma unroll
            for (int mt = 0; mt < 2; ++mt)
#pragma unroll
                for (int nt = 0; nt < 4; ++nt)
                    wmma::mma_sync(acc[mt][nt], af[mt], bf[nt], acc[mt][nt]);
        }
        __syncthreads();   // slot consumed before next overwrite
    }

    // ---- epilogue: stage each 16x16 accum tile through smem, fuse bias(+GELU)
    __syncthreads();
    float* patch = smem + warp * 16 * 20;     // per-warp 16x20 patch (reuses stage 0)
    const int prow = lane >> 1;
    const int pcol = (lane & 1) * 8;
#pragma unroll
    for (int mt = 0; mt < 2; ++mt) {
#pragma unroll
        for (int nt = 0; nt < 4; ++nt) {
            wmma::store_matrix_sync(patch, acc[mt][nt], 20, wmma::mem_row_major);
            __syncwarp();
            const int gm = m0 + wm * 32 + mt * 16 + prow;
            const int gn = n0 + wn * 64 + nt * 16 + pcol;
            float* op = Oe + (size_t)gm * ldN + gn;
            float f[8];
#pragma unroll
            for (int j = 0; j < 8; ++j) {
                float x = patch[prow * 20 + pcol + j] + __ldg(be + gn + j);
                if (GELU) {
                    x = gelu_tanh(x);
                    x = rna_tf32(x);          // H is GEMM2's A operand
                }
                f[j] = x;
            }
            *reinterpret_cast<float4*>(op)     = make_float4(f[0], f[1], f[2], f[3]);
            *reinterpret_cast<float4*>(op + 4) = make_float4(f[4], f[5], f[6], f[7]);
            __syncwarp();
        }
    }
}

// ---------------------------------------------------------------------------
// kernel_launch: round(x,w1,w2) -> GEMM1 (GELU+round -> g_H) -> GEMM2 -> out
// ---------------------------------------------------------------------------
extern "C" void kernel_launch(void* const* d_in, const int* in_sizes, int n_in,
                              void* d_out, int out_size) {
    (void)in_sizes; (void)n_in; (void)out_size;
    const float* inputs = (const float*)d_in[0];
    const float* w1     = (const float*)d_in[1];
    const float* b1     = (const float*)d_in[2];
    const float* w2     = (const float*)d_in[3];
    const float* b2     = (const float*)d_in[4];
    float* out = (float*)d_out;

    void *hp, *xp, *w1p, *w2p;
    cudaGetSymbolAddress(&hp,  g_H);
    cudaGetSymbolAddress(&xp,  g_Xr);
    cudaGetSymbolAddress(&w1p, g_W1r);
    cudaGetSymbolAddress(&w2p, g_W2r);
    float* H   = (float*)hp;
    float* Xr  = (float*)xp;
    float* W1r = (float*)w1p;
    float* W2r = (float*)w2p;

    const size_t nX  = (size_t)EXP_E * EXP_C * EXP_D / 4;
    const size_t nW1 = (size_t)EXP_E * EXP_D * EXP_F / 4;
    const size_t nW2 = (size_t)EXP_E * EXP_F * EXP_D / 4;
    round_tf32_pass<<<2048, 256>>>((const float4*)inputs, (float4*)Xr,  nX);
    round_tf32_pass<<<8192, 256>>>((const float4*)w1,     (float4*)W1r, nW1);
    round_tf32_pass<<<8192, 256>>>((const float4*)w2,     (float4*)W2r, nW2);

    cudaFuncSetAttribute(moe_gemm_tf32<true>,
                         cudaFuncAttributeMaxDynamicSharedMemorySize, SMEM_BYTES);
    cudaFuncSetAttribute(moe_gemm_tf32<false>,
                         cudaFuncAttributeMaxDynamicSharedMemorySize, SMEM_BYTES);

    dim3 g1(EXP_C / BM, EXP_F / BN, EXP_E);   // (16, 64, 8)
    moe_gemm_tf32<true><<<g1, 256, SMEM_BYTES>>>(Xr, W1r, b1, H, EXP_D, EXP_F);

    dim3 g2(EXP_C / BM, EXP_D / BN, EXP_E);   // (16, 16, 8)
    moe_gemm_tf32<false><<<g2, 256, SMEM_BYTES>>>(H, W2r, b2, out, EXP_F, EXP_D);
}

// round 5
// speedup vs baseline: 1.1143x; 1.1055x over previous
#include <cuda_runtime.h>
#include <mma.h>
#include <cstdint>
#include <math.h>

using namespace nvcuda;

// ---------------------------------------------------------------------------
// 8-expert FFN, fp32: per expert [2048x2048]@[2048x8192] -> GELU -> @[8192x2048]
// Portable tf32 mma path (compute_103: no tcgen05/TMA).
// R5: warp tile 64x64 (CUTLASS sm80-tf32 shape), CTA 128x256, 1 CTA/SM,
//     single __syncthreads per k-tile. Operands pre-rounded RNA to tf32.
// ---------------------------------------------------------------------------
#define EXP_E 8
#define EXP_C 2048
#define EXP_D 2048
#define EXP_F 8192

__device__ __align__(256) float g_H  [(size_t)EXP_E * EXP_C * EXP_F];
__device__ __align__(256) float g_Xr [(size_t)EXP_E * EXP_C * EXP_D];
__device__ __align__(256) float g_W1r[(size_t)EXP_E * EXP_D * EXP_F];
__device__ __align__(256) float g_W2r[(size_t)EXP_E * EXP_F * EXP_D];

// ---------------------------------------------------------------------------
// Tiling: CTA 128x256x16, 8 warps of 64x64 (warp grid 2x4)
// ---------------------------------------------------------------------------
#define BM 128
#define BN 256
#define BK 16
#define STAGES 4
#define A_STRIDE 20                         // 16 + 4 pad
#define B_STRIDE 260                        // 256 + 4 pad
#define A_FLOATS (BM * A_STRIDE)            // 2560
#define B_FLOATS (BK * B_STRIDE)            // 4160
#define STAGE_FLOATS (A_FLOATS + B_FLOATS)  // 6720
#define SMEM_BYTES (STAGES * STAGE_FLOATS * 4)   // 107520

// ---------------------------------------------------------------------------
// Helpers
// ---------------------------------------------------------------------------
__device__ __forceinline__ uint32_t smem_u32(const void* p) {
    uint32_t a;
    asm("{ .reg .u64 t; cvta.to.shared.u64 t, %1; cvt.u32.u64 %0, t; }"
        : "=r"(a) : "l"(p));
    return a;
}

#define CP_ASYNC_CG(dst_u32, src_ptr) \
    asm volatile("cp.async.cg.shared.global [%0], [%1], 16;" \
                 :: "r"(dst_u32), "l"(src_ptr) : "memory")
#define CP_ASYNC_COMMIT() asm volatile("cp.async.commit_group;" ::: "memory")
#define CP_ASYNC_WAIT(n)  asm volatile("cp.async.wait_group %0;" :: "n"(n) : "memory")

__device__ __forceinline__ float rna_tf32(float f) {
    unsigned u = __float_as_uint(f);
    u = (u + 0x1000u) & 0xffffe000u;
    return __uint_as_float(u);
}

__device__ __forceinline__ float gelu_tanh(float x) {
    float u = 0.7978845608028654f * fmaf(0.044715f * x, x * x, x);
    return 0.5f * x * (1.0f + tanhf(u));
}

__global__ void __launch_bounds__(256)
round_tf32_pass(const float4* __restrict__ in, float4* __restrict__ out, size_t n4) {
    size_t i = (size_t)blockIdx.x * blockDim.x + threadIdx.x;
    size_t stride = (size_t)gridDim.x * blockDim.x;
    for (; i < n4; i += stride) {
        float4 v = in[i];
        v.x = rna_tf32(v.x); v.y = rna_tf32(v.y);
        v.z = rna_tf32(v.z); v.w = rna_tf32(v.w);
        out[i] = v;
    }
}

// ---------------------------------------------------------------------------
// Batched GEMM: Out[e][m][n] = epi( sum_k A[e][m][k]*B[e][k][n] + bias[e][n] )
//   grid = (2048/BM, ldN/BN, E), 256 threads, 1 CTA/SM
// ---------------------------------------------------------------------------
template <bool GELU>
__global__ void __launch_bounds__(256, 1)
moe_gemm_tf32(const float* __restrict__ A, const float* __restrict__ B,
              const float* __restrict__ bias, float* __restrict__ Out,
              int K, int ldN)
{
    extern __shared__ float smem[];
    const int tid  = threadIdx.x;
    const int warp = tid >> 5;
    const int lane = tid & 31;
    const int e  = blockIdx.z;
    const int m0 = blockIdx.x * BM;
    const int n0 = blockIdx.y * BN;
    const int KT = K / BK;

    const float* Ae = A    + (size_t)e * EXP_C * K;
    const float* Be = B    + (size_t)e * K * ldN;
    const float* be = bias + (size_t)e * ldN;
    float*       Oe = Out  + (size_t)e * EXP_C * ldN;

    // warp grid 2(M) x 4(N); warp tile 64x64 = 4x4 wmma 16x16 tiles
    const int wm = warp >> 2;   // 0..1
    const int wn = warp & 3;    // 0..3

    // cp.async coordinates (256 threads)
    const int arow   = tid >> 2;   // 0..63 (+64 second rep); 4 float4 per A row
    const int achunk = tid & 3;
    const int brow   = tid >> 6;   // 0..3 (+4,+8,+12 reps); 64 float4 per B row
    const int bchunk = tid & 63;

    const float* a_src0 = Ae + (size_t)(m0 + arow) * K + achunk * 4;
    const float* b_src0 = Be + (size_t)brow * ldN + n0 + bchunk * 4;

    wmma::fragment<wmma::accumulator, 16, 16, 8, float> acc[4][4];
#pragma unroll
    for (int mt = 0; mt < 4; ++mt)
#pragma unroll
        for (int nt = 0; nt < 4; ++nt)
            wmma::fill_fragment(acc[mt][nt], 0.0f);

    auto issue_tile = [&](int t) {
        const int s = t & (STAGES - 1);
        float* sA = smem + s * STAGE_FLOATS;
        float* sB = sA + A_FLOATS;
        const int k0 = t * BK;
        // A: 128 rows x 16 floats
        const float* asrc = a_src0 + k0;
        uint32_t adst = smem_u32(sA + arow * A_STRIDE + achunk * 4);
        CP_ASYNC_CG(adst, asrc);
        CP_ASYNC_CG(adst + 64 * A_STRIDE * 4, asrc + (size_t)64 * K);
        // B: 16 k-rows x 256 floats
        const float* bsrc = b_src0 + (size_t)k0 * ldN;
        uint32_t bdst = smem_u32(sB + brow * B_STRIDE + bchunk * 4);
#pragma unroll
        for (int r = 0; r < 4; ++r)
            CP_ASYNC_CG(bdst + r * 4 * B_STRIDE * 4, bsrc + (size_t)r * 4 * ldN);
    };

    // prefetch STAGES-1 tiles
#pragma unroll
    for (int t = 0; t < STAGES - 1; ++t) {
        issue_tile(t);
        CP_ASYNC_COMMIT();
    }

    for (int t = 0; t < KT; ++t) {
        CP_ASYNC_WAIT(STAGES - 2);     // tile t resident
        __syncthreads();               // all warps done reading stage (t-1)%4
        if (t + STAGES - 1 < KT) issue_tile(t + STAGES - 1);
        CP_ASYNC_COMMIT();             // uniform group count

        const int s = t & (STAGES - 1);
        const float* sA = smem + s * STAGE_FLOATS;
        const float* sB = sA + A_FLOATS;

#pragma unroll
        for (int kk = 0; kk < 2; ++kk) {
            wmma::fragment<wmma::matrix_a, 16, 16, 8,
                           wmma::precision::tf32, wmma::row_major> af[4];
            wmma::fragment<wmma::matrix_b, 16, 16, 8,
                           wmma::precision::tf32, wmma::row_major> bf[4];
#pragma unroll
            for (int mt = 0; mt < 4; ++mt)
                wmma::load_matrix_sync(
                    af[mt], sA + (wm * 64 + mt * 16) * A_STRIDE + kk * 8, A_STRIDE);
#pragma unroll
            for (int nt = 0; nt < 4; ++nt)
                wmma::load_matrix_sync(
                    bf[nt], sB + kk * 8 * B_STRIDE + wn * 64 + nt * 16, B_STRIDE);
#pragma unroll
            for (int mt = 0; mt < 4; ++mt)
#pragma unroll
                for (int nt = 0; nt < 4; ++nt)
                    wmma::mma_sync(acc[mt][nt], af[mt], bf[nt], acc[mt][nt]);
        }
    }

    // ---- epilogue: stage 16x16 tiles through smem, fuse bias (+GELU+round) ----
    __syncthreads();
    float* patch = smem + warp * 16 * 20;
    const int prow = lane >> 1;
    const int pcol = (lane & 1) * 8;
#pragma unroll
    for (int mt = 0; mt < 4; ++mt) {
#pragma unroll
        for (int nt = 0; nt < 4; ++nt) {
            wmma::store_matrix_sync(patch, acc[mt][nt], 20, wmma::mem_row_major);
            __syncwarp();
            const int gm = m0 + wm * 64 + mt * 16 + prow;
            const int gn = n0 + wn * 64 + nt * 16 + pcol;
            float* op = Oe + (size_t)gm * ldN + gn;
            float f[8];
#pragma unroll
            for (int j = 0; j < 8; ++j) {
                float x = patch[prow * 20 + pcol + j] + __ldg(be + gn + j);
                if (GELU) {
                    x = gelu_tanh(x);
                    x = rna_tf32(x);     // H feeds GEMM2 as A operand
                }
                f[j] = x;
            }
            *reinterpret_cast<float4*>(op)     = make_float4(f[0], f[1], f[2], f[3]);
            *reinterpret_cast<float4*>(op + 4) = make_float4(f[4], f[5], f[6], f[7]);
            __syncwarp();
        }
    }
}

// ---------------------------------------------------------------------------
// kernel_launch
// ---------------------------------------------------------------------------
extern "C" void kernel_launch(void* const* d_in, const int* in_sizes, int n_in,
                              void* d_out, int out_size) {
    (void)in_sizes; (void)n_in; (void)out_size;
    const float* inputs = (const float*)d_in[0];
    const float* w1     = (const float*)d_in[1];
    const float* b1     = (const float*)d_in[2];
    const float* w2     = (const float*)d_in[3];
    const float* b2     = (const float*)d_in[4];
    float* out = (float*)d_out;

    void *hp, *xp, *w1p, *w2p;
    cudaGetSymbolAddress(&hp,  g_H);
    cudaGetSymbolAddress(&xp,  g_Xr);
    cudaGetSymbolAddress(&w1p, g_W1r);
    cudaGetSymbolAddress(&w2p, g_W2r);
    float* H   = (float*)hp;
    float* Xr  = (float*)xp;
    float* W1r = (float*)w1p;
    float* W2r = (float*)w2p;

    const size_t nX  = (size_t)EXP_E * EXP_C * EXP_D / 4;
    const size_t nW1 = (size_t)EXP_E * EXP_D * EXP_F / 4;
    const size_t nW2 = (size_t)EXP_E * EXP_F * EXP_D / 4;
    round_tf32_pass<<<2048, 256>>>((const float4*)inputs, (float4*)Xr,  nX);
    round_tf32_pass<<<8192, 256>>>((const float4*)w1,     (float4*)W1r, nW1);
    round_tf32_pass<<<8192, 256>>>((const float4*)w2,     (float4*)W2r, nW2);

    cudaFuncSetAttribute(moe_gemm_tf32<true>,
                         cudaFuncAttributeMaxDynamicSharedMemorySize, SMEM_BYTES);
    cudaFuncSetAttribute(moe_gemm_tf32<false>,
                         cudaFuncAttributeMaxDynamicSharedMemorySize, SMEM_BYTES);

    dim3 g1(EXP_C / BM, EXP_F / BN, EXP_E);   // (16, 32, 8)
    moe_gemm_tf32<true><<<g1, 256, SMEM_BYTES>>>(Xr, W1r, b1, H, EXP_D, EXP_F);

    dim3 g2(EXP_C / BM, EXP_D / BN, EXP_E);   // (16, 8, 8)
    moe_gemm_tf32<false><<<g2, 256, SMEM_BYTES>>>(H, W2r, b2, out, EXP_F, EXP_D);
}

// round 6
// speedup vs baseline: 2.2248x; 1.9965x over previous
#include <cuda_runtime.h>
#include <cstdint>
#include <math.h>

// ---------------------------------------------------------------------------
// 8-expert FFN, fp32: per expert [2048x2048]@[2048x8192] -> GELU -> @[8192x2048]
// compute_103 portable path (no tcgen05/TMA): raw mma.sync.m16n8k8.tf32 with
// ldmatrix.x4 fragment loads from XOR-swizzled SMEM. B operand pre-transposed
// to K-major packed tiles by the rounding pre-pass.
// ---------------------------------------------------------------------------
#define EXP_E 8
#define EXP_C 2048
#define EXP_D 2048
#define EXP_F 8192

__device__ __align__(256) float g_H  [(size_t)EXP_E * EXP_C * EXP_F];  // [E][C][F]
__device__ __align__(256) float g_Xr [(size_t)EXP_E * EXP_C * EXP_D];  // rounded X
__device__ __align__(256) float g_W1t[(size_t)EXP_E * EXP_D * EXP_F];  // [E][D/16][F][16]
__device__ __align__(256) float g_W2t[(size_t)EXP_E * EXP_F * EXP_D];  // [E][F/16][D][16]

// ---------------------------------------------------------------------------
// Tiling: CTA 128x256x16, 8 warps (2x4 grid of 64x64 warp tiles)
// SMEM tiles stored as [row][16 floats] with chunk swizzle c ^= (row>>1)&3.
// ---------------------------------------------------------------------------
#define BM 128
#define BN 256
#define BK 16
#define STAGES 4
#define A_BYTES (BM * 16 * 4)               // 8192
#define B_BYTES (BN * 16 * 4)               // 16384
#define STAGE_BYTES (A_BYTES + B_BYTES)     // 24576
#define SMEM_BYTES (STAGES * STAGE_BYTES)   // 98304

// ---------------------------------------------------------------------------
// Helpers
// ---------------------------------------------------------------------------
__device__ __forceinline__ uint32_t smem_u32(const void* p) {
    uint32_t a;
    asm("{ .reg .u64 t; cvta.to.shared.u64 t, %1; cvt.u32.u64 %0, t; }"
        : "=r"(a) : "l"(p));
    return a;
}

#define CP_ASYNC_CG(dst_u32, src_ptr) \
    asm volatile("cp.async.cg.shared.global [%0], [%1], 16;" \
                 :: "r"(dst_u32), "l"(src_ptr) : "memory")
#define CP_ASYNC_COMMIT() asm volatile("cp.async.commit_group;" ::: "memory")
#define CP_ASYNC_WAIT(n)  asm volatile("cp.async.wait_group %0;" :: "n"(n) : "memory")

// ldmatrix x4: threads 0-7/8-15/16-23/24-31 provide row addrs of matrices 0-3;
// result reg k of thread t = element (row=t>>2, tf32col=t&3) of matrix k.
#define LDSM_X4(r, addr) \
    asm volatile("ldmatrix.sync.aligned.m8n8.x4.shared.b16 {%0,%1,%2,%3}, [%4];" \
                 : "=r"((r)[0]), "=r"((r)[1]), "=r"((r)[2]), "=r"((r)[3]) \
                 : "r"(addr))

// mma.m16n8k8 tf32: A row-major frag {a0..a3}, B col-major frag {b0,b1}
__device__ __forceinline__ void mma_tf32(float* d, const uint32_t* a,
                                         uint32_t b0, uint32_t b1) {
    asm volatile(
        "mma.sync.aligned.m16n8k8.row.col.f32.tf32.tf32.f32 "
        "{%0,%1,%2,%3}, {%4,%5,%6,%7}, {%8,%9}, {%0,%1,%2,%3};"
        : "+f"(d[0]), "+f"(d[1]), "+f"(d[2]), "+f"(d[3])
        : "r"(a[0]), "r"(a[1]), "r"(a[2]), "r"(a[3]), "r"(b0), "r"(b1));
}

__device__ __forceinline__ float rna_tf32(float f) {
    unsigned u = __float_as_uint(f);
    u = (u + 0x1000u) & 0xffffe000u;
    return __uint_as_float(u);
}

__device__ __forceinline__ float gelu_tanh(float x) {
    float u = 0.7978845608028654f * fmaf(0.044715f * x, x * x, x);
    return 0.5f * x * (1.0f + tanhf(u));
}

// One-shot RNA rounding (X operand).
__global__ void __launch_bounds__(256)
round_tf32_pass(const float4* __restrict__ in, float4* __restrict__ out, size_t n4) {
    size_t i = (size_t)blockIdx.x * blockDim.x + threadIdx.x;
    size_t stride = (size_t)gridDim.x * blockDim.x;
    for (; i < n4; i += stride) {
        float4 v = in[i];
        v.x = rna_tf32(v.x); v.y = rna_tf32(v.y);
        v.z = rna_tf32(v.z); v.w = rna_tf32(v.w);
        out[i] = v;
    }
}

// Round + transpose-pack weights: W[e][k][n] -> Wt[e][k/16][n][16].
// Reads coalesced along n; writes 64B-contiguous per thread.
__global__ void __launch_bounds__(256)
round_transpose_pack(const float* __restrict__ W, float* __restrict__ Wt,
                     int K, int N) {
    const int n  = blockIdx.x * 256 + threadIdx.x;
    const int kt = blockIdx.y;
    const int e  = blockIdx.z;
    const float* src = W + ((size_t)e * K + (size_t)kt * 16) * N + n;
    float v[16];
#pragma unroll
    for (int j = 0; j < 16; ++j) v[j] = rna_tf32(src[(size_t)j * N]);
    float* dst = Wt + (((size_t)e * (K / 16) + kt) * N + n) * 16;
#pragma unroll
    for (int j = 0; j < 16; j += 4)
        *reinterpret_cast<float4*>(dst + j) = make_float4(v[j], v[j+1], v[j+2], v[j+3]);
}

// ---------------------------------------------------------------------------
// Batched GEMM: Out[e][m][n] = epi( sum_k A[e][m][k]*B[e][k][n] + bias[e][n] )
//   A:  [E][2048][K] row-major (pre-rounded)
//   Bt: [E][K/16][ldN][16] K-major packed (pre-rounded)
//   grid = (2048/BM, ldN/BN, E), 256 threads
// ---------------------------------------------------------------------------
template <bool GELU>
__global__ void __launch_bounds__(256, 1)
moe_gemm_tf32(const float* __restrict__ A, const float* __restrict__ Bt,
              const float* __restrict__ bias, float* __restrict__ Out,
              int K, int ldN)
{
    extern __shared__ char smem[];
    const int tid  = threadIdx.x;
    const int warp = tid >> 5;
    const int lane = tid & 31;
    const int e  = blockIdx.z;
    const int m0 = blockIdx.x * BM;
    const int n0 = blockIdx.y * BN;
    const int KT = K / BK;

    const float* Ae  = A  + (size_t)e * EXP_C * K;
    const float* Bte = Bt + (size_t)e * (K / 16) * ldN * 16 + (size_t)n0 * 16;
    const float* be  = bias + (size_t)e * ldN;
    float*       Oe  = Out  + (size_t)e * EXP_C * ldN;

    const uint32_t sbase = smem_u32(smem);

    // warp grid 2(M) x 4(N); warp tile 64x64 = 4 m16 x 8 n8 mma tiles
    const int wm = warp >> 2;
    const int wn = warp & 3;

    // cp.async coords: row = tid>>2 (+64*rep), chunk = tid&3, swizzled
    const int crow   = tid >> 2;
    const int cchunk = tid & 3;

    // ldmatrix per-thread geometry
    const int lrow = ((lane >> 3) & 1) * 8 + (lane & 7);  // row within 16-row group
    const int lhi  = lane >> 4;                            // chunk low bit

    // precomputed swizzled fragment row offsets (bytes within tile)
    uint32_t aoff[4], boff[4];
    int aswz[4], bswz[4];
#pragma unroll
    for (int i = 0; i < 4; ++i) {
        int ra = wm * 64 + i * 16 + lrow;
        aoff[i] = (uint32_t)ra * 64;  aswz[i] = (ra >> 1) & 3;
        int rb = wn * 64 + i * 16 + lrow;
        boff[i] = (uint32_t)rb * 64;  bswz[i] = (rb >> 1) & 3;
    }

    float acc[4][8][4];
#pragma unroll
    for (int mt = 0; mt < 4; ++mt)
#pragma unroll
        for (int nt = 0; nt < 8; ++nt)
#pragma unroll
            for (int j = 0; j < 4; ++j) acc[mt][nt][j] = 0.0f;

    auto issue_tile = [&](int t) {
        const int s = t & (STAGES - 1);
        const uint32_t sA = sbase + s * STAGE_BYTES;
        const uint32_t sB = sA + A_BYTES;
        // A: 128 rows x 16 floats
        const float* asrc = Ae + (size_t)(m0 + crow) * K + t * BK + cchunk * 4;
#pragma unroll
        for (int rep = 0; rep < 2; ++rep) {
            int row = crow + rep * 64;
            uint32_t dst = sA + row * 64 + ((cchunk ^ ((row >> 1) & 3)) * 16);
            CP_ASYNC_CG(dst, asrc + (size_t)rep * 64 * K);
        }
        // B: contiguous packed block, 256 rows x 16 floats
        const float* bsrc = Bte + (size_t)t * ldN * 16 + crow * 16 + cchunk * 4;
#pragma unroll
        for (int rep = 0; rep < 4; ++rep) {
            int row = crow + rep * 64;
            uint32_t dst = sB + row * 64 + ((cchunk ^ ((row >> 1) & 3)) * 16);
            CP_ASYNC_CG(dst, bsrc + (size_t)rep * 64 * 16);
        }
    };

#pragma unroll
    for (int t = 0; t < STAGES - 1; ++t) {
        issue_tile(t);
        CP_ASYNC_COMMIT();
    }

    for (int t = 0; t < KT; ++t) {
        CP_ASYNC_WAIT(STAGES - 2);
        __syncthreads();
        if (t + STAGES - 1 < KT) issue_tile(t + STAGES - 1);
        CP_ASYNC_COMMIT();

        const int s = t & (STAGES - 1);
        const uint32_t sA = sbase + s * STAGE_BYTES;
        const uint32_t sB = sA + A_BYTES;

#pragma unroll
        for (int kk = 0; kk < 2; ++kk) {
            const int cbase = kk * 2 + lhi;       // logical chunk (no carry w/ |)
            uint32_t af[4][4], bf[4][4];
#pragma unroll
            for (int mt = 0; mt < 4; ++mt)
                LDSM_X4(af[mt], sA + aoff[mt] + (uint32_t)((cbase ^ aswz[mt]) * 16));
#pragma unroll
            for (int np = 0; np < 4; ++np)
                LDSM_X4(bf[np], sB + boff[np] + (uint32_t)((cbase ^ bswz[np]) * 16));
            // bf[np]: r0=b0(n8 tile 2np), r1=b0(tile 2np+1), r2=b1(2np), r3=b1(2np+1)
#pragma unroll
            for (int mt = 0; mt < 4; ++mt)
#pragma unroll
                for (int nt = 0; nt < 8; ++nt)
                    mma_tf32(acc[mt][nt], af[mt],
                             bf[nt >> 1][nt & 1], bf[nt >> 1][2 + (nt & 1)]);
        }
    }

    // ---- epilogue: direct reg -> gmem, fused bias (+GELU+round) ----
    const int g     = lane >> 2;
    const int cpair = (lane & 3) * 2;
    float2 bv[8];
#pragma unroll
    for (int nt = 0; nt < 8; ++nt)
        bv[nt] = *reinterpret_cast<const float2*>(be + n0 + wn * 64 + nt * 8 + cpair);

#pragma unroll
    for (int mt = 0; mt < 4; ++mt) {
#pragma unroll
        for (int h = 0; h < 2; ++h) {
            const int grow = m0 + wm * 64 + mt * 16 + g + h * 8;
            float* op = Oe + (size_t)grow * ldN + n0 + wn * 64 + cpair;
#pragma unroll
            for (int nt = 0; nt < 8; ++nt) {
                float x0 = acc[mt][nt][h * 2]     + bv[nt].x;
                float x1 = acc[mt][nt][h * 2 + 1] + bv[nt].y;
                if (GELU) {
                    x0 = rna_tf32(gelu_tanh(x0));   // H feeds GEMM2 as A
                    x1 = rna_tf32(gelu_tanh(x1));
                }
                *reinterpret_cast<float2*>(op + nt * 8) = make_float2(x0, x1);
            }
        }
    }
}

// ---------------------------------------------------------------------------
// kernel_launch
// ---------------------------------------------------------------------------
extern "C" void kernel_launch(void* const* d_in, const int* in_sizes, int n_in,
                              void* d_out, int out_size) {
    (void)in_sizes; (void)n_in; (void)out_size;
    const float* inputs = (const float*)d_in[0];
    const float* w1     = (const float*)d_in[1];
    const float* b1     = (const float*)d_in[2];
    const float* w2     = (const float*)d_in[3];
    const float* b2     = (const float*)d_in[4];
    float* out = (float*)d_out;

    void *hp, *xp, *w1p, *w2p;
    cudaGetSymbolAddress(&hp,  g_H);
    cudaGetSymbolAddress(&xp,  g_Xr);
    cudaGetSymbolAddress(&w1p, g_W1t);
    cudaGetSymbolAddress(&w2p, g_W2t);
    float* H   = (float*)hp;
    float* Xr  = (float*)xp;
    float* W1t = (float*)w1p;
    float* W2t = (float*)w2p;

    const size_t nX = (size_t)EXP_E * EXP_C * EXP_D / 4;
    round_tf32_pass<<<2048, 256>>>((const float4*)inputs, (float4*)Xr, nX);

    dim3 t1(EXP_F / 256, EXP_D / 16, EXP_E);   // W1: K=D, N=F
    round_transpose_pack<<<t1, 256>>>(w1, W1t, EXP_D, EXP_F);
    dim3 t2(EXP_D / 256, EXP_F / 16, EXP_E);   // W2: K=F, N=D
    round_transpose_pack<<<t2, 256>>>(w2, W2t, EXP_F, EXP_D);

    cudaFuncSetAttribute(moe_gemm_tf32<true>,
                         cudaFuncAttributeMaxDynamicSharedMemorySize, SMEM_BYTES);
    cudaFuncSetAttribute(moe_gemm_tf32<false>,
                         cudaFuncAttributeMaxDynamicSharedMemorySize, SMEM_BYTES);

    dim3 g1(EXP_C / BM, EXP_F / BN, EXP_E);    // (16, 32, 8)
    moe_gemm_tf32<true><<<g1, 256, SMEM_BYTES>>>(Xr, W1t, b1, H, EXP_D, EXP_F);

    dim3 g2(EXP_C / BM, EXP_D / BN, EXP_E);    // (16, 8, 8)
    moe_gemm_tf32<false><<<g2, 256, SMEM_BYTES>>>(H, W2t, b2, out, EXP_F, EXP_D);
}

// round 7
// speedup vs baseline: 2.2524x; 1.0124x over previous
#include <cuda_runtime.h>
#include <cstdint>
#include <math.h>

// ---------------------------------------------------------------------------
// 8-expert FFN, fp32: per expert [2048x2048]@[2048x8192] -> GELU -> @[8192x2048]
// compute_103 portable path: raw mma.sync.m16n8k8.tf32 + ldmatrix.x4 from
// XOR-swizzled SMEM. R7: all address math hoisted out of the mainloop
// (running gmem pointers, precomputed in-stage offsets, kk1 = kk0 ^ 32),
// both kk fragment sets front-loaded before the MMA burst.
// ---------------------------------------------------------------------------
#define EXP_E 8
#define EXP_C 2048
#define EXP_D 2048
#define EXP_F 8192

__device__ __align__(256) float g_H  [(size_t)EXP_E * EXP_C * EXP_F];  // [E][C][F]
__device__ __align__(256) float g_Xr [(size_t)EXP_E * EXP_C * EXP_D];  // rounded X
__device__ __align__(256) float g_W1t[(size_t)EXP_E * EXP_D * EXP_F];  // [E][D/16][F][16]
__device__ __align__(256) float g_W2t[(size_t)EXP_E * EXP_F * EXP_D];  // [E][F/16][D][16]

#define BM 128
#define BN 256
#define BK 16
#define STAGES 4
#define A_BYTES (BM * 16 * 4)               // 8192
#define B_BYTES (BN * 16 * 4)               // 16384
#define STAGE_BYTES (A_BYTES + B_BYTES)     // 24576
#define SMEM_BYTES (STAGES * STAGE_BYTES)   // 98304

// ---------------------------------------------------------------------------
// Helpers
// ---------------------------------------------------------------------------
__device__ __forceinline__ uint32_t smem_u32(const void* p) {
    uint32_t a;
    asm("{ .reg .u64 t; cvta.to.shared.u64 t, %1; cvt.u32.u64 %0, t; }"
        : "=r"(a) : "l"(p));
    return a;
}

#define CP_ASYNC_CG(dst_u32, src_ptr) \
    asm volatile("cp.async.cg.shared.global [%0], [%1], 16;" \
                 :: "r"(dst_u32), "l"(src_ptr) : "memory")
#define CP_ASYNC_COMMIT() asm volatile("cp.async.commit_group;" ::: "memory")
#define CP_ASYNC_WAIT(n)  asm volatile("cp.async.wait_group %0;" :: "n"(n) : "memory")

#define LDSM_X4(r, addr) \
    asm volatile("ldmatrix.sync.aligned.m8n8.x4.shared.b16 {%0,%1,%2,%3}, [%4];" \
                 : "=r"((r)[0]), "=r"((r)[1]), "=r"((r)[2]), "=r"((r)[3]) \
                 : "r"(addr))

__device__ __forceinline__ void mma_tf32(float* d, const uint32_t* a,
                                         uint32_t b0, uint32_t b1) {
    asm volatile(
        "mma.sync.aligned.m16n8k8.row.col.f32.tf32.tf32.f32 "
        "{%0,%1,%2,%3}, {%4,%5,%6,%7}, {%8,%9}, {%0,%1,%2,%3};"
        : "+f"(d[0]), "+f"(d[1]), "+f"(d[2]), "+f"(d[3])
        : "r"(a[0]), "r"(a[1]), "r"(a[2]), "r"(a[3]), "r"(b0), "r"(b1));
}

__device__ __forceinline__ float rna_tf32(float f) {
    unsigned u = __float_as_uint(f);
    u = (u + 0x1000u) & 0xffffe000u;
    return __uint_as_float(u);
}

__device__ __forceinline__ float gelu_tanh(float x) {
    float u = 0.7978845608028654f * fmaf(0.044715f * x, x * x, x);
    return 0.5f * x * (1.0f + tanhf(u));
}

__global__ void __launch_bounds__(256)
round_tf32_pass(const float4* __restrict__ in, float4* __restrict__ out, size_t n4) {
    size_t i = (size_t)blockIdx.x * blockDim.x + threadIdx.x;
    size_t stride = (size_t)gridDim.x * blockDim.x;
    for (; i < n4; i += stride) {
        float4 v = in[i];
        v.x = rna_tf32(v.x); v.y = rna_tf32(v.y);
        v.z = rna_tf32(v.z); v.w = rna_tf32(v.w);
        out[i] = v;
    }
}

// Round + transpose-pack weights: W[e][k][n] -> Wt[e][k/16][n][16].
__global__ void __launch_bounds__(256)
round_transpose_pack(const float* __restrict__ W, float* __restrict__ Wt,
                     int K, int N) {
    const int n  = blockIdx.x * 256 + threadIdx.x;
    const int kt = blockIdx.y;
    const int e  = blockIdx.z;
    const float* src = W + ((size_t)e * K + (size_t)kt * 16) * N + n;
    float v[16];
#pragma unroll
    for (int j = 0; j < 16; ++j) v[j] = rna_tf32(src[(size_t)j * N]);
    float* dst = Wt + (((size_t)e * (K / 16) + kt) * N + n) * 16;
#pragma unroll
    for (int j = 0; j < 16; j += 4)
        *reinterpret_cast<float4*>(dst + j) = make_float4(v[j], v[j+1], v[j+2], v[j+3]);
}

// ---------------------------------------------------------------------------
// Batched GEMM: Out[e][m][n] = epi( sum_k A[e][m][k]*B[e][k][n] + bias[e][n] )
//   A:  [E][2048][K] row-major (pre-rounded)
//   Bt: [E][K/16][ldN][16] K-major packed (pre-rounded)
// ---------------------------------------------------------------------------
template <bool GELU>
__global__ void __launch_bounds__(256, 1)
moe_gemm_tf32(const float* __restrict__ A, const float* __restrict__ Bt,
              const float* __restrict__ bias, float* __restrict__ Out,
              int K, int ldN)
{
    extern __shared__ char smem[];
    const int tid  = threadIdx.x;
    const int warp = tid >> 5;
    const int lane = tid & 31;
    const int e  = blockIdx.z;
    const int m0 = blockIdx.x * BM;
    const int n0 = blockIdx.y * BN;
    const int KT = K / BK;

    const float* Ae  = A  + (size_t)e * EXP_C * K;
    const float* Bte = Bt + (size_t)e * (K / 16) * ldN * 16 + (size_t)n0 * 16;
    const float* be  = bias + (size_t)e * ldN;
    float*       Oe  = Out  + (size_t)e * EXP_C * ldN;

    const uint32_t sbase = smem_u32(smem);

    const int wm = warp >> 2;    // warp grid 2(M) x 4(N), warp tile 64x64
    const int wn = warp & 3;

    // ---- loop-invariant cp.async geometry ----
    const int crow   = tid >> 2;
    const int cchunk = tid & 3;
    const int cswz   = (crow >> 1) & 3;        // rep*64 never changes bits 1..2
    const uint32_t a_dst0 = (uint32_t)(crow * 64 + ((cchunk ^ cswz) * 16));
    const uint32_t a_dst1 = a_dst0 + 64u * 64u;
    uint32_t b_dst[4];
#pragma unroll
    for (int rep = 0; rep < 4; ++rep)
        b_dst[rep] = (uint32_t)(A_BYTES + (crow + rep * 64) * 64 + ((cchunk ^ cswz) * 16));

    // running gmem pointers (advance per issued tile)
    const float* a_run = Ae  + (size_t)(m0 + crow) * K + cchunk * 4;
    const float* b_run = Bte + (size_t)crow * 16 + cchunk * 4;

    // ---- loop-invariant ldmatrix geometry (kk=0; kk=1 is ^32) ----
    const int lrow = ((lane >> 3) & 1) * 8 + (lane & 7);
    const int lhi  = lane >> 4;
    uint32_t afrag[4], bfrag[4];
#pragma unroll
    for (int i = 0; i < 4; ++i) {
        int ra = wm * 64 + i * 16 + lrow;
        afrag[i] = (uint32_t)(ra * 64 + ((lhi ^ ((ra >> 1) & 3)) * 16));
        int rb = wn * 64 + i * 16 + lrow;
        bfrag[i] = (uint32_t)(A_BYTES + rb * 64 + ((lhi ^ ((rb >> 1) & 3)) * 16));
    }

    float acc[4][8][4];
#pragma unroll
    for (int mt = 0; mt < 4; ++mt)
#pragma unroll
        for (int nt = 0; nt < 8; ++nt)
#pragma unroll
            for (int j = 0; j < 4; ++j) acc[mt][nt][j] = 0.0f;

    auto issue_tile = [&](int s) {
        const uint32_t st = sbase + (uint32_t)s * STAGE_BYTES;
        CP_ASYNC_CG(st + a_dst0, a_run);
        CP_ASYNC_CG(st + a_dst1, a_run + (size_t)64 * K);
#pragma unroll
        for (int rep = 0; rep < 4; ++rep)
            CP_ASYNC_CG(st + b_dst[rep], b_run + rep * 64 * 16);
        a_run += BK;
        b_run += (size_t)ldN * 16;
    };

#pragma unroll
    for (int t = 0; t < STAGES - 1; ++t) {
        issue_tile(t);
        CP_ASYNC_COMMIT();
    }

    for (int t = 0; t < KT; ++t) {
        CP_ASYNC_WAIT(STAGES - 2);
        __syncthreads();
        if (t + STAGES - 1 < KT) issue_tile((t + STAGES - 1) & (STAGES - 1));
        CP_ASYNC_COMMIT();

        const uint32_t sA = sbase + (uint32_t)(t & (STAGES - 1)) * STAGE_BYTES;

        // front-load BOTH kk fragment sets, then one long MMA burst
        uint32_t af0[4][4], bf0[4][4], af1[4][4], bf1[4][4];
#pragma unroll
        for (int mt = 0; mt < 4; ++mt) LDSM_X4(af0[mt], sA + afrag[mt]);
#pragma unroll
        for (int np = 0; np < 4; ++np) LDSM_X4(bf0[np], sA + bfrag[np]);
#pragma unroll
        for (int mt = 0; mt < 4; ++mt) LDSM_X4(af1[mt], sA + (afrag[mt] ^ 32u));
#pragma unroll
        for (int np = 0; np < 4; ++np) LDSM_X4(bf1[np], sA + (bfrag[np] ^ 32u));

#pragma unroll
        for (int mt = 0; mt < 4; ++mt)
#pragma unroll
            for (int nt = 0; nt < 8; ++nt)
                mma_tf32(acc[mt][nt], af0[mt],
                         bf0[nt >> 1][nt & 1], bf0[nt >> 1][2 + (nt & 1)]);
#pragma unroll
        for (int mt = 0; mt < 4; ++mt)
#pragma unroll
            for (int nt = 0; nt < 8; ++nt)
                mma_tf32(acc[mt][nt], af1[mt],
                         bf1[nt >> 1][nt & 1], bf1[nt >> 1][2 + (nt & 1)]);
    }

    // ---- epilogue: direct reg -> gmem, fused bias (+GELU+round) ----
    const int g     = lane >> 2;
    const int cpair = (lane & 3) * 2;
    float2 bv[8];
#pragma unroll
    for (int nt = 0; nt < 8; ++nt)
        bv[nt] = *reinterpret_cast<const float2*>(be + n0 + wn * 64 + nt * 8 + cpair);

#pragma unroll
    for (int mt = 0; mt < 4; ++mt) {
#pragma unroll
        for (int h = 0; h < 2; ++h) {
            const int grow = m0 + wm * 64 + mt * 16 + g + h * 8;
            float* op = Oe + (size_t)grow * ldN + n0 + wn * 64 + cpair;
#pragma unroll
            for (int nt = 0; nt < 8; ++nt) {
                float x0 = acc[mt][nt][h * 2]     + bv[nt].x;
                float x1 = acc[mt][nt][h * 2 + 1] + bv[nt].y;
                if (GELU) {
                    x0 = rna_tf32(gelu_tanh(x0));   // H feeds GEMM2 as A
                    x1 = rna_tf32(gelu_tanh(x1));
                }
                *reinterpret_cast<float2*>(op + nt * 8) = make_float2(x0, x1);
            }
        }
    }
}

// ---------------------------------------------------------------------------
// kernel_launch
// ---------------------------------------------------------------------------
extern "C" void kernel_launch(void* const* d_in, const int* in_sizes, int n_in,
                              void* d_out, int out_size) {
    (void)in_sizes; (void)n_in; (void)out_size;
    const float* inputs = (const float*)d_in[0];
    const float* w1     = (const float*)d_in[1];
    const float* b1     = (const float*)d_in[2];
    const float* w2     = (const float*)d_in[3];
    const float* b2     = (const float*)d_in[4];
    float* out = (float*)d_out;

    void *hp, *xp, *w1p, *w2p;
    cudaGetSymbolAddress(&hp,  g_H);
    cudaGetSymbolAddress(&xp,  g_Xr);
    cudaGetSymbolAddress(&w1p, g_W1t);
    cudaGetSymbolAddress(&w2p, g_W2t);
    float* H   = (float*)hp;
    float* Xr  = (float*)xp;
    float* W1t = (float*)w1p;
    float* W2t = (float*)w2p;

    const size_t nX = (size_t)EXP_E * EXP_C * EXP_D / 4;
    round_tf32_pass<<<2048, 256>>>((const float4*)inputs, (float4*)Xr, nX);

    dim3 t1(EXP_F / 256, EXP_D / 16, EXP_E);   // W1: K=D, N=F
    round_transpose_pack<<<t1, 256>>>(w1, W1t, EXP_D, EXP_F);
    dim3 t2(EXP_D / 256, EXP_F / 16, EXP_E);   // W2: K=F, N=D
    round_transpose_pack<<<t2, 256>>>(w2, W2t, EXP_F, EXP_D);

    cudaFuncSetAttribute(moe_gemm_tf32<true>,
                         cudaFuncAttributeMaxDynamicSharedMemorySize, SMEM_BYTES);
    cudaFuncSetAttribute(moe_gemm_tf32<false>,
                         cudaFuncAttributeMaxDynamicSharedMemorySize, SMEM_BYTES);

    dim3 g1(EXP_C / BM, EXP_F / BN, EXP_E);    // (16, 32, 8)
    moe_gemm_tf32<true><<<g1, 256, SMEM_BYTES>>>(Xr, W1t, b1, H, EXP_D, EXP_F);

    dim3 g2(EXP_C / BM, EXP_D / BN, EXP_E);    // (16, 8, 8)
    moe_gemm_tf32<false><<<g2, 256, SMEM_BYTES>>>(H, W2t, b2, out, EXP_F, EXP_D);
}

// round 8
// speedup vs baseline: 2.3094x; 1.0253x over previous
#include <cuda_runtime.h>
#include <cstdint>
#include <math.h>

// ---------------------------------------------------------------------------
// 8-expert FFN, fp32: per expert [2048x2048]@[2048x8192] -> GELU -> @[8192x2048]
// compute_103 portable path: raw mma.sync.m16n8k8.tf32 + ldmatrix.x4 from
// XOR-swizzled SMEM. R8: CTA 128x128 / 128 threads / 2 CTAs per SM so two
// independent CTAs cover each other's barrier+LDSM bubbles.
// ---------------------------------------------------------------------------
#define EXP_E 8
#define EXP_C 2048
#define EXP_D 2048
#define EXP_F 8192

__device__ __align__(256) float g_H  [(size_t)EXP_E * EXP_C * EXP_F];  // [E][C][F]
__device__ __align__(256) float g_Xr [(size_t)EXP_E * EXP_C * EXP_D];  // rounded X
__device__ __align__(256) float g_W1t[(size_t)EXP_E * EXP_D * EXP_F];  // [E][D/16][F][16]
__device__ __align__(256) float g_W2t[(size_t)EXP_E * EXP_F * EXP_D];  // [E][F/16][D][16]

#define BM 128
#define BN 128
#define BK 16
#define STAGES 4
#define A_BYTES (BM * 16 * 4)               // 8192
#define B_BYTES (BN * 16 * 4)               // 8192
#define STAGE_BYTES (A_BYTES + B_BYTES)     // 16384
#define SMEM_BYTES (STAGES * STAGE_BYTES)   // 65536 per CTA (2 CTAs = 128KB/SM)

// ---------------------------------------------------------------------------
// Helpers
// ---------------------------------------------------------------------------
__device__ __forceinline__ uint32_t smem_u32(const void* p) {
    uint32_t a;
    asm("{ .reg .u64 t; cvta.to.shared.u64 t, %1; cvt.u32.u64 %0, t; }"
        : "=r"(a) : "l"(p));
    return a;
}

#define CP_ASYNC_CG(dst_u32, src_ptr) \
    asm volatile("cp.async.cg.shared.global [%0], [%1], 16;" \
                 :: "r"(dst_u32), "l"(src_ptr) : "memory")
#define CP_ASYNC_COMMIT() asm volatile("cp.async.commit_group;" ::: "memory")
#define CP_ASYNC_WAIT(n)  asm volatile("cp.async.wait_group %0;" :: "n"(n) : "memory")

#define LDSM_X4(r, addr) \
    asm volatile("ldmatrix.sync.aligned.m8n8.x4.shared.b16 {%0,%1,%2,%3}, [%4];" \
                 : "=r"((r)[0]), "=r"((r)[1]), "=r"((r)[2]), "=r"((r)[3]) \
                 : "r"(addr))

__device__ __forceinline__ void mma_tf32(float* d, const uint32_t* a,
                                         uint32_t b0, uint32_t b1) {
    asm volatile(
        "mma.sync.aligned.m16n8k8.row.col.f32.tf32.tf32.f32 "
        "{%0,%1,%2,%3}, {%4,%5,%6,%7}, {%8,%9}, {%0,%1,%2,%3};"
        : "+f"(d[0]), "+f"(d[1]), "+f"(d[2]), "+f"(d[3])
        : "r"(a[0]), "r"(a[1]), "r"(a[2]), "r"(a[3]), "r"(b0), "r"(b1));
}

__device__ __forceinline__ float rna_tf32(float f) {
    unsigned u = __float_as_uint(f);
    u = (u + 0x1000u) & 0xffffe000u;
    return __uint_as_float(u);
}

__device__ __forceinline__ float gelu_tanh(float x) {
    float u = 0.7978845608028654f * fmaf(0.044715f * x, x * x, x);
    return 0.5f * x * (1.0f + tanhf(u));
}

__global__ void __launch_bounds__(256)
round_tf32_pass(const float4* __restrict__ in, float4* __restrict__ out, size_t n4) {
    size_t i = (size_t)blockIdx.x * blockDim.x + threadIdx.x;
    size_t stride = (size_t)gridDim.x * blockDim.x;
    for (; i < n4; i += stride) {
        float4 v = in[i];
        v.x = rna_tf32(v.x); v.y = rna_tf32(v.y);
        v.z = rna_tf32(v.z); v.w = rna_tf32(v.w);
        out[i] = v;
    }
}

// Round + transpose-pack weights: W[e][k][n] -> Wt[e][k/16][n][16].
__global__ void __launch_bounds__(256)
round_transpose_pack(const float* __restrict__ W, float* __restrict__ Wt,
                     int K, int N) {
    const int n  = blockIdx.x * 256 + threadIdx.x;
    const int kt = blockIdx.y;
    const int e  = blockIdx.z;
    const float* src = W + ((size_t)e * K + (size_t)kt * 16) * N + n;
    float v[16];
#pragma unroll
    for (int j = 0; j < 16; ++j) v[j] = rna_tf32(src[(size_t)j * N]);
    float* dst = Wt + (((size_t)e * (K / 16) + kt) * N + n) * 16;
#pragma unroll
    for (int j = 0; j < 16; j += 4)
        *reinterpret_cast<float4*>(dst + j) = make_float4(v[j], v[j+1], v[j+2], v[j+3]);
}

// ---------------------------------------------------------------------------
// Batched GEMM: Out[e][m][n] = epi( sum_k A[e][m][k]*B[e][k][n] + bias[e][n] )
//   A:  [E][2048][K] row-major (pre-rounded)
//   Bt: [E][K/16][ldN][16] K-major packed (pre-rounded)
//   CTA 128x128x16, 128 threads (warp grid 2x2 of 64x64), 2 CTAs/SM.
// ---------------------------------------------------------------------------
template <bool GELU>
__global__ void __launch_bounds__(128, 2)
moe_gemm_tf32(const float* __restrict__ A, const float* __restrict__ Bt,
              const float* __restrict__ bias, float* __restrict__ Out,
              int K, int ldN)
{
    extern __shared__ char smem[];
    const int tid  = threadIdx.x;
    const int warp = tid >> 5;
    const int lane = tid & 31;
    const int e  = blockIdx.z;
    const int m0 = blockIdx.x * BM;
    const int n0 = blockIdx.y * BN;
    const int KT = K / BK;

    const float* Ae  = A  + (size_t)e * EXP_C * K;
    const float* Bte = Bt + (size_t)e * (K / 16) * ldN * 16 + (size_t)n0 * 16;
    const float* be  = bias + (size_t)e * ldN;
    float*       Oe  = Out  + (size_t)e * EXP_C * ldN;

    const uint32_t sbase = smem_u32(smem);

    const int wm = warp >> 1;    // warp grid 2(M) x 2(N), warp tile 64x64
    const int wn = warp & 1;

    // ---- loop-invariant cp.async geometry (128 threads) ----
    const int crow   = tid >> 2;           // 0..31, reps at +32
    const int cchunk = tid & 3;
    const int cswz   = (crow >> 1) & 3;    // +32 never touches bits 1..2
    uint32_t a_dst[4], b_dst[4];
#pragma unroll
    for (int rep = 0; rep < 4; ++rep) {
        a_dst[rep] = (uint32_t)((crow + rep * 32) * 64 + ((cchunk ^ cswz) * 16));
        b_dst[rep] = a_dst[rep] + A_BYTES;
    }

    // running gmem pointers
    const float* a_run = Ae  + (size_t)(m0 + crow) * K + cchunk * 4;
    const float* b_run = Bte + (size_t)crow * 16 + cchunk * 4;

    // ---- loop-invariant ldmatrix geometry (kk=0; kk=1 is ^32) ----
    const int lrow = ((lane >> 3) & 1) * 8 + (lane & 7);
    const int lhi  = lane >> 4;
    uint32_t afrag[4], bfrag[4];
#pragma unroll
    for (int i = 0; i < 4; ++i) {
        int ra = wm * 64 + i * 16 + lrow;
        afrag[i] = (uint32_t)(ra * 64 + ((lhi ^ ((ra >> 1) & 3)) * 16));
        int rb = wn * 64 + i * 16 + lrow;
        bfrag[i] = (uint32_t)(A_BYTES + rb * 64 + ((lhi ^ ((rb >> 1) & 3)) * 16));
    }

    float acc[4][8][4];
#pragma unroll
    for (int mt = 0; mt < 4; ++mt)
#pragma unroll
        for (int nt = 0; nt < 8; ++nt)
#pragma unroll
            for (int j = 0; j < 4; ++j) acc[mt][nt][j] = 0.0f;

    auto issue_tile = [&](int s) {
        const uint32_t st = sbase + (uint32_t)s * STAGE_BYTES;
#pragma unroll
        for (int rep = 0; rep < 4; ++rep)
            CP_ASYNC_CG(st + a_dst[rep], a_run + (size_t)rep * 32 * K);
#pragma unroll
        for (int rep = 0; rep < 4; ++rep)
            CP_ASYNC_CG(st + b_dst[rep], b_run + rep * 32 * 16);
        a_run += BK;
        b_run += (size_t)ldN * 16;
    };

#pragma unroll
    for (int t = 0; t < STAGES - 1; ++t) {
        issue_tile(t);
        CP_ASYNC_COMMIT();
    }

    for (int t = 0; t < KT; ++t) {
        CP_ASYNC_WAIT(STAGES - 2);
        __syncthreads();
        if (t + STAGES - 1 < KT) issue_tile((t + STAGES - 1) & (STAGES - 1));
        CP_ASYNC_COMMIT();

        const uint32_t sA = sbase + (uint32_t)(t & (STAGES - 1)) * STAGE_BYTES;

        // front-load both kk fragment sets, then one long MMA burst
        uint32_t af0[4][4], bf0[4][4], af1[4][4], bf1[4][4];
#pragma unroll
        for (int mt = 0; mt < 4; ++mt) LDSM_X4(af0[mt], sA + afrag[mt]);
#pragma unroll
        for (int np = 0; np < 4; ++np) LDSM_X4(bf0[np], sA + bfrag[np]);
#pragma unroll
        for (int mt = 0; mt < 4; ++mt) LDSM_X4(af1[mt], sA + (afrag[mt] ^ 32u));
#pragma unroll
        for (int np = 0; np < 4; ++np) LDSM_X4(bf1[np], sA + (bfrag[np] ^ 32u));

#pragma unroll
        for (int mt = 0; mt < 4; ++mt)
#pragma unroll
            for (int nt = 0; nt < 8; ++nt)
                mma_tf32(acc[mt][nt], af0[mt],
                         bf0[nt >> 1][nt & 1], bf0[nt >> 1][2 + (nt & 1)]);
#pragma unroll
        for (int mt = 0; mt < 4; ++mt)
#pragma unroll
            for (int nt = 0; nt < 8; ++nt)
                mma_tf32(acc[mt][nt], af1[mt],
                         bf1[nt >> 1][nt & 1], bf1[nt >> 1][2 + (nt & 1)]);
    }

    // ---- epilogue: direct reg -> gmem, fused bias (+GELU+round) ----
    const int g     = lane >> 2;
    const int cpair = (lane & 3) * 2;
    float2 bv[8];
#pragma unroll
    for (int nt = 0; nt < 8; ++nt)
        bv[nt] = *reinterpret_cast<const float2*>(be + n0 + wn * 64 + nt * 8 + cpair);

#pragma unroll
    for (int mt = 0; mt < 4; ++mt) {
#pragma unroll
        for (int h = 0; h < 2; ++h) {
            const int grow = m0 + wm * 64 + mt * 16 + g + h * 8;
            float* op = Oe + (size_t)grow * ldN + n0 + wn * 64 + cpair;
#pragma unroll
            for (int nt = 0; nt < 8; ++nt) {
                float x0 = acc[mt][nt][h * 2]     + bv[nt].x;
                float x1 = acc[mt][nt][h * 2 + 1] + bv[nt].y;
                if (GELU) {
                    x0 = rna_tf32(gelu_tanh(x0));   // H feeds GEMM2 as A
                    x1 = rna_tf32(gelu_tanh(x1));
                }
                *reinterpret_cast<float2*>(op + nt * 8) = make_float2(x0, x1);
            }
        }
    }
}

// ---------------------------------------------------------------------------
// kernel_launch
// ---------------------------------------------------------------------------
extern "C" void kernel_launch(void* const* d_in, const int* in_sizes, int n_in,
                              void* d_out, int out_size) {
    (void)in_sizes; (void)n_in; (void)out_size;
    const float* inputs = (const float*)d_in[0];
    const float* w1     = (const float*)d_in[1];
    const float* b1     = (const float*)d_in[2];
    const float* w2     = (const float*)d_in[3];
    const float* b2     = (const float*)d_in[4];
    float* out = (float*)d_out;

    void *hp, *xp, *w1p, *w2p;
    cudaGetSymbolAddress(&hp,  g_H);
    cudaGetSymbolAddress(&xp,  g_Xr);
    cudaGetSymbolAddress(&w1p, g_W1t);
    cudaGetSymbolAddress(&w2p, g_W2t);
    float* H   = (float*)hp;
    float* Xr  = (float*)xp;
    float* W1t = (float*)w1p;
    float* W2t = (float*)w2p;

    const size_t nX = (size_t)EXP_E * EXP_C * EXP_D / 4;
    round_tf32_pass<<<2048, 256>>>((const float4*)inputs, (float4*)Xr, nX);

    dim3 t1(EXP_F / 256, EXP_D / 16, EXP_E);   // W1: K=D, N=F
    round_transpose_pack<<<t1, 256>>>(w1, W1t, EXP_D, EXP_F);
    dim3 t2(EXP_D / 256, EXP_F / 16, EXP_E);   // W2: K=F, N=D
    round_transpose_pack<<<t2, 256>>>(w2, W2t, EXP_F, EXP_D);

    cudaFuncSetAttribute(moe_gemm_tf32<true>,
                         cudaFuncAttributeMaxDynamicSharedMemorySize, SMEM_BYTES);
    cudaFuncSetAttribute(moe_gemm_tf32<false>,
                         cudaFuncAttributeMaxDynamicSharedMemorySize, SMEM_BYTES);

    dim3 g1(EXP_C / BM, EXP_F / BN, EXP_E);    // (16, 64, 8)
    moe_gemm_tf32<true><<<g1, 128, SMEM_BYTES>>>(Xr, W1t, b1, H, EXP_D, EXP_F);

    dim3 g2(EXP_C / BM, EXP_D / BN, EXP_E);    // (16, 16, 8)
    moe_gemm_tf32<false><<<g2, 128, SMEM_BYTES>>>(H, W2t, b2, out, EXP_F, EXP_D);
}

// round 10
// speedup vs baseline: 2.5320x; 1.0964x over previous
#include <cuda_runtime.h>
#include <cstdint>
#include <math.h>

// ---------------------------------------------------------------------------
// 8-expert FFN, fp32: per expert [2048x2048]@[2048x8192] -> GELU -> @[8192x2048]
// compute_103 portable path: raw mma.sync.m16n8k8.tf32 + ldmatrix.x4 from
// XOR-swizzled SMEM. R10 = R9 (BK=32, 3 stages, 256-MMA bursts, kk double-
// buffered fragments, 2 CTAs/SM) with the stage-index wrap bug fixed
// (proper modular fill-stage counter; R9 wrote cp.async past smem).
// ---------------------------------------------------------------------------
#define EXP_E 8
#define EXP_C 2048
#define EXP_D 2048
#define EXP_F 8192

__device__ __align__(256) float g_H  [(size_t)EXP_E * EXP_C * EXP_F];  // [E][C][F]
__device__ __align__(256) float g_Xr [(size_t)EXP_E * EXP_C * EXP_D];  // rounded X
__device__ __align__(256) float g_W1t[(size_t)EXP_E * EXP_D * EXP_F];  // [E][D/32][F][32]
__device__ __align__(256) float g_W2t[(size_t)EXP_E * EXP_F * EXP_D];  // [E][F/32][D][32]

#define BM 128
#define BN 128
#define BK 32
#define STAGES 3
#define ROW_BYTES 128                       // 32 floats per k-row
#define A_BYTES (BM * ROW_BYTES)            // 16384
#define B_BYTES (BN * ROW_BYTES)            // 16384
#define STAGE_BYTES (A_BYTES + B_BYTES)     // 32768
#define SMEM_BYTES (STAGES * STAGE_BYTES)   // 98304/CTA; 2 CTAs = 192KB/SM

// ---------------------------------------------------------------------------
// Helpers
// ---------------------------------------------------------------------------
__device__ __forceinline__ uint32_t smem_u32(const void* p) {
    uint32_t a;
    asm("{ .reg .u64 t; cvta.to.shared.u64 t, %1; cvt.u32.u64 %0, t; }"
        : "=r"(a) : "l"(p));
    return a;
}

#define CP_ASYNC_CG(dst_u32, src_ptr) \
    asm volatile("cp.async.cg.shared.global [%0], [%1], 16;" \
                 :: "r"(dst_u32), "l"(src_ptr) : "memory")
#define CP_ASYNC_COMMIT() asm volatile("cp.async.commit_group;" ::: "memory")
#define CP_ASYNC_WAIT(n)  asm volatile("cp.async.wait_group %0;" :: "n"(n) : "memory")

#define LDSM_X4(r, addr) \
    asm volatile("ldmatrix.sync.aligned.m8n8.x4.shared.b16 {%0,%1,%2,%3}, [%4];" \
                 : "=r"((r)[0]), "=r"((r)[1]), "=r"((r)[2]), "=r"((r)[3]) \
                 : "r"(addr))

__device__ __forceinline__ void mma_tf32(float* d, const uint32_t* a,
                                         uint32_t b0, uint32_t b1) {
    asm volatile(
        "mma.sync.aligned.m16n8k8.row.col.f32.tf32.tf32.f32 "
        "{%0,%1,%2,%3}, {%4,%5,%6,%7}, {%8,%9}, {%0,%1,%2,%3};"
        : "+f"(d[0]), "+f"(d[1]), "+f"(d[2]), "+f"(d[3])
        : "r"(a[0]), "r"(a[1]), "r"(a[2]), "r"(a[3]), "r"(b0), "r"(b1));
}

__device__ __forceinline__ float rna_tf32(float f) {
    unsigned u = __float_as_uint(f);
    u = (u + 0x1000u) & 0xffffe000u;
    return __uint_as_float(u);
}

__device__ __forceinline__ float gelu_tanh(float x) {
    float u = 0.7978845608028654f * fmaf(0.044715f * x, x * x, x);
    return 0.5f * x * (1.0f + tanhf(u));
}

__global__ void __launch_bounds__(256)
round_tf32_pass(const float4* __restrict__ in, float4* __restrict__ out, size_t n4) {
    size_t i = (size_t)blockIdx.x * blockDim.x + threadIdx.x;
    size_t stride = (size_t)gridDim.x * blockDim.x;
    for (; i < n4; i += stride) {
        float4 v = in[i];
        v.x = rna_tf32(v.x); v.y = rna_tf32(v.y);
        v.z = rna_tf32(v.z); v.w = rna_tf32(v.w);
        out[i] = v;
    }
}

// Round + transpose-pack weights 32-wide: W[e][k][n] -> Wt[e][k/32][n][32].
__global__ void __launch_bounds__(256)
round_transpose_pack32(const float* __restrict__ W, float* __restrict__ Wt,
                       int K, int N) {
    const int n  = blockIdx.x * 256 + threadIdx.x;
    const int kt = blockIdx.y;
    const int e  = blockIdx.z;
    const float* src = W + ((size_t)e * K + (size_t)kt * 32) * N + n;
    float* dst = Wt + (((size_t)e * (K / 32) + kt) * N + n) * 32;
#pragma unroll
    for (int j = 0; j < 32; j += 4) {
        float4 v;
        v.x = rna_tf32(src[(size_t)(j + 0) * N]);
        v.y = rna_tf32(src[(size_t)(j + 1) * N]);
        v.z = rna_tf32(src[(size_t)(j + 2) * N]);
        v.w = rna_tf32(src[(size_t)(j + 3) * N]);
        *reinterpret_cast<float4*>(dst + j) = v;
    }
}

// ---------------------------------------------------------------------------
// Batched GEMM: Out[e][m][n] = epi( sum_k A[e][m][k]*B[e][k][n] + bias[e][n] )
//   A:  [E][2048][K] row-major (pre-rounded)
//   Bt: [E][K/32][ldN][32] K-major packed (pre-rounded)
//   CTA 128x128x32, 128 threads (warp grid 2x2 of 64x64), 2 CTAs/SM.
// ---------------------------------------------------------------------------
template <bool GELU>
__global__ void __launch_bounds__(128, 2)
moe_gemm_tf32(const float* __restrict__ A, const float* __restrict__ Bt,
              const float* __restrict__ bias, float* __restrict__ Out,
              int K, int ldN)
{
    extern __shared__ char smem[];
    const int tid  = threadIdx.x;
    const int warp = tid >> 5;
    const int lane = tid & 31;
    const int e  = blockIdx.z;
    const int m0 = blockIdx.x * BM;
    const int n0 = blockIdx.y * BN;
    const int KT = K / BK;

    const float* Ae  = A  + (size_t)e * EXP_C * K;
    const float* Bte = Bt + (size_t)e * (K / 32) * ldN * 32 + (size_t)n0 * 32;
    const float* be  = bias + (size_t)e * ldN;
    float*       Oe  = Out  + (size_t)e * EXP_C * ldN;

    const uint32_t sbase = smem_u32(smem);

    const int wm = warp >> 1;    // warp grid 2(M) x 2(N), warp tile 64x64
    const int wn = warp & 1;

    // ---- cp.async geometry: row = tid>>3 (+16*rep), chunk = tid&7 ----
    const int crow   = tid >> 3;              // 0..15
    const int cchunk = tid & 7;               // 8 x 16B per 128B row
    const int cswz   = crow & 7;              // rep*16 keeps row bits 0..2
    const uint32_t a_dst0 = (uint32_t)(crow * ROW_BYTES + ((cchunk ^ cswz) * 16));

    // running gmem pointers
    const float* a_run = Ae  + (size_t)(m0 + crow) * K + cchunk * 4;
    const float* b_run = Bte + (size_t)crow * 32 + cchunk * 4;

    // ---- ldmatrix geometry (kk=0; kk-step address is base ^ (kk*32)) ----
    const int lrow = ((lane >> 3) & 1) * 8 + (lane & 7);   // 0..15
    const int lhi  = lane >> 4;                             // chunk bit 0
    uint32_t afrag[4], bfrag[4];
#pragma unroll
    for (int i = 0; i < 4; ++i) {
        int ra = wm * 64 + i * 16 + lrow;
        afrag[i] = (uint32_t)(ra * ROW_BYTES + ((lhi ^ (ra & 7)) * 16));
        int rb = wn * 64 + i * 16 + lrow;
        bfrag[i] = (uint32_t)(A_BYTES + rb * ROW_BYTES + ((lhi ^ (rb & 7)) * 16));
    }

    float acc[4][8][4];
#pragma unroll
    for (int mt = 0; mt < 4; ++mt)
#pragma unroll
        for (int nt = 0; nt < 8; ++nt)
#pragma unroll
            for (int j = 0; j < 4; ++j) acc[mt][nt][j] = 0.0f;

    auto issue_tile = [&](int stg) {
        const uint32_t st = sbase + (uint32_t)stg * STAGE_BYTES;
#pragma unroll
        for (int rep = 0; rep < 8; ++rep)
            CP_ASYNC_CG(st + a_dst0 + rep * 16u * ROW_BYTES,
                        a_run + (size_t)rep * 16 * K);
#pragma unroll
        for (int rep = 0; rep < 8; ++rep)
            CP_ASYNC_CG(st + A_BYTES + a_dst0 + rep * 16u * ROW_BYTES,
                        b_run + rep * 16 * 32);
        a_run += BK;
        b_run += (size_t)ldN * 32;
    };

#pragma unroll
    for (int t = 0; t < STAGES - 1; ++t) {   // fills stages 0..STAGES-2
        issue_tile(t);
        CP_ASYNC_COMMIT();
    }

    int s  = 0;            // stage to consume
    int si = STAGES - 1;   // next stage to fill (FIXED: proper modular counter)
    for (int t = 0; t < KT; ++t) {
        CP_ASYNC_WAIT(STAGES - 2);
        __syncthreads();
        if (t + STAGES - 1 < KT) {
            issue_tile(si);
            if (++si == STAGES) si = 0;
        }
        CP_ASYNC_COMMIT();

        const uint32_t sA = sbase + (uint32_t)s * STAGE_BYTES;
        if (++s == STAGES) s = 0;

        // 4 kk-steps, fragments double-buffered
        uint32_t af[2][4][4], bf[2][4][4];
#pragma unroll
        for (int i = 0; i < 4; ++i) LDSM_X4(af[0][i], sA + afrag[i]);
#pragma unroll
        for (int i = 0; i < 4; ++i) LDSM_X4(bf[0][i], sA + bfrag[i]);

#pragma unroll
        for (int kk = 0; kk < 4; ++kk) {
            const int cur = kk & 1, nxt = cur ^ 1;
            if (kk < 3) {
                const uint32_t x = (uint32_t)(kk + 1) * 32u;
#pragma unroll
                for (int i = 0; i < 4; ++i) LDSM_X4(af[nxt][i], sA + (afrag[i] ^ x));
#pragma unroll
                for (int i = 0; i < 4; ++i) LDSM_X4(bf[nxt][i], sA + (bfrag[i] ^ x));
            }
#pragma unroll
            for (int mt = 0; mt < 4; ++mt)
#pragma unroll
                for (int nt = 0; nt < 8; ++nt)
                    mma_tf32(acc[mt][nt], af[cur][mt],
                             bf[cur][nt >> 1][nt & 1], bf[cur][nt >> 1][2 + (nt & 1)]);
        }
    }

    // ---- epilogue: direct reg -> gmem, fused bias (+GELU+round) ----
    const int g     = lane >> 2;
    const int cpair = (lane & 3) * 2;
    float2 bv[8];
#pragma unroll
    for (int nt = 0; nt < 8; ++nt)
        bv[nt] = *reinterpret_cast<const float2*>(be + n0 + wn * 64 + nt * 8 + cpair);

#pragma unroll
    for (int mt = 0; mt < 4; ++mt) {
#pragma unroll
        for (int h = 0; h < 2; ++h) {
            const int grow = m0 + wm * 64 + mt * 16 + g + h * 8;
            float* op = Oe + (size_t)grow * ldN + n0 + wn * 64 + cpair;
#pragma unroll
            for (int nt = 0; nt < 8; ++nt) {
                float x0 = acc[mt][nt][h * 2]     + bv[nt].x;
                float x1 = acc[mt][nt][h * 2 + 1] + bv[nt].y;
                if (GELU) {
                    x0 = rna_tf32(gelu_tanh(x0));   // H feeds GEMM2 as A
                    x1 = rna_tf32(gelu_tanh(x1));
                }
                *reinterpret_cast<float2*>(op + nt * 8) = make_float2(x0, x1);
            }
        }
    }
}

// ---------------------------------------------------------------------------
// kernel_launch
// ---------------------------------------------------------------------------
extern "C" void kernel_launch(void* const* d_in, const int* in_sizes, int n_in,
                              void* d_out, int out_size) {
    (void)in_sizes; (void)n_in; (void)out_size;
    const float* inputs = (const float*)d_in[0];
    const float* w1     = (const float*)d_in[1];
    const float* b1     = (const float*)d_in[2];
    const float* w2     = (const float*)d_in[3];
    const float* b2     = (const float*)d_in[4];
    float* out = (float*)d_out;

    void *hp, *xp, *w1p, *w2p;
    cudaGetSymbolAddress(&hp,  g_H);
    cudaGetSymbolAddress(&xp,  g_Xr);
    cudaGetSymbolAddress(&w1p, g_W1t);
    cudaGetSymbolAddress(&w2p, g_W2t);
    float* H   = (float*)hp;
    float* Xr  = (float*)xp;
    float* W1t = (float*)w1p;
    float* W2t = (float*)w2p;

    const size_t nX = (size_t)EXP_E * EXP_C * EXP_D / 4;
    round_tf32_pass<<<2048, 256>>>((const float4*)inputs, (float4*)Xr, nX);

    dim3 t1(EXP_F / 256, EXP_D / 32, EXP_E);   // W1: K=D, N=F
    round_transpose_pack32<<<t1, 256>>>(w1, W1t, EXP_D, EXP_F);
    dim3 t2(EXP_D / 256, EXP_F / 32, EXP_E);   // W2: K=F, N=D
    round_transpose_pack32<<<t2, 256>>>(w2, W2t, EXP_F, EXP_D);

    cudaFuncSetAttribute(moe_gemm_tf32<true>,
                         cudaFuncAttributeMaxDynamicSharedMemorySize, SMEM_BYTES);
    cudaFuncSetAttribute(moe_gemm_tf32<false>,
                         cudaFuncAttributeMaxDynamicSharedMemorySize, SMEM_BYTES);

    dim3 g1(EXP_C / BM, EXP_F / BN, EXP_E);    // (16, 64, 8)
    moe_gemm_tf32<true><<<g1, 128, SMEM_BYTES>>>(Xr, W1t, b1, H, EXP_D, EXP_F);

    dim3 g2(EXP_C / BM, EXP_D / BN, EXP_E);    // (16, 16, 8)
    moe_gemm_tf32<false><<<g2, 128, SMEM_BYTES>>>(H, W2t, b2, out, EXP_F, EXP_D);
}

// round 11
// speedup vs baseline: 5.2171x; 2.0605x over previous
#include <cuda_runtime.h>
#include <cuda_fp16.h>
#include <cstdint>
#include <math.h>

// ---------------------------------------------------------------------------
// 8-expert FFN, fp32: per expert [2048x2048]@[2048x8192] -> GELU -> @[8192x2048]
// compute_103 portable path. R11: fp16 operands (same 11-bit mantissa as tf32,
// values all in fp16 normal range, fp32 accumulate) with mma.m16n8k16 ->
// 2x tensor rate, half the bytes. BK=64, 3 stages, 2 CTAs/SM.
// ---------------------------------------------------------------------------
#define EXP_E 8
#define EXP_C 2048
#define EXP_D 2048
#define EXP_F 8192

__device__ __align__(256) __half g_H  [(size_t)EXP_E * EXP_C * EXP_F];  // gelu(X@W1+b1)
__device__ __align__(256) __half g_Xh [(size_t)EXP_E * EXP_C * EXP_D];  // half X
__device__ __align__(256) __half g_W1h[(size_t)EXP_E * EXP_D * EXP_F];  // [E][D/64][F][64]
__device__ __align__(256) __half g_W2h[(size_t)EXP_E * EXP_F * EXP_D];  // [E][F/64][D][64]

#define BM 128
#define BN 128
#define BK 64
#define STAGES 3
#define ROW_BYTES 128                       // 64 halves per k-row
#define A_BYTES (BM * ROW_BYTES)            // 16384
#define B_BYTES (BN * ROW_BYTES)            // 16384
#define STAGE_BYTES (A_BYTES + B_BYTES)     // 32768
#define SMEM_BYTES (STAGES * STAGE_BYTES)   // 98304/CTA; 2 CTAs = 192KB/SM

// ---------------------------------------------------------------------------
// Helpers
// ---------------------------------------------------------------------------
__device__ __forceinline__ uint32_t smem_u32(const void* p) {
    uint32_t a;
    asm("{ .reg .u64 t; cvta.to.shared.u64 t, %1; cvt.u32.u64 %0, t; }"
        : "=r"(a) : "l"(p));
    return a;
}

#define CP_ASYNC_CG(dst_u32, src_ptr) \
    asm volatile("cp.async.cg.shared.global [%0], [%1], 16;" \
                 :: "r"(dst_u32), "l"(src_ptr) : "memory")
#define CP_ASYNC_COMMIT() asm volatile("cp.async.commit_group;" ::: "memory")
#define CP_ASYNC_WAIT(n)  asm volatile("cp.async.wait_group %0;" :: "n"(n) : "memory")

#define LDSM_X4(r, addr) \
    asm volatile("ldmatrix.sync.aligned.m8n8.x4.shared.b16 {%0,%1,%2,%3}, [%4];" \
                 : "=r"((r)[0]), "=r"((r)[1]), "=r"((r)[2]), "=r"((r)[3]) \
                 : "r"(addr))

// fp16 MMA, fp32 accumulate
__device__ __forceinline__ void mma_f16(float* d, const uint32_t* a,
                                        uint32_t b0, uint32_t b1) {
    asm volatile(
        "mma.sync.aligned.m16n8k16.row.col.f32.f16.f16.f32 "
        "{%0,%1,%2,%3}, {%4,%5,%6,%7}, {%8,%9}, {%0,%1,%2,%3};"
        : "+f"(d[0]), "+f"(d[1]), "+f"(d[2]), "+f"(d[3])
        : "r"(a[0]), "r"(a[1]), "r"(a[2]), "r"(a[3]), "r"(b0), "r"(b1));
}

__device__ __forceinline__ float gelu_tanh(float x) {
    float u = 0.7978845608028654f * fmaf(0.044715f * x, x * x, x);
    return 0.5f * x * (1.0f + tanhf(u));
}

// Convert X: fp32 -> fp16 (RNE), 4 elements/thread iteration.
__global__ void __launch_bounds__(256)
to_half_pass(const float4* __restrict__ in, uint2* __restrict__ out, size_t n4) {
    size_t i = (size_t)blockIdx.x * blockDim.x + threadIdx.x;
    size_t stride = (size_t)gridDim.x * blockDim.x;
    for (; i < n4; i += stride) {
        float4 v = in[i];
        __half2 h0 = __floats2half2_rn(v.x, v.y);
        __half2 h1 = __floats2half2_rn(v.z, v.w);
        uint2 u;
        u.x = *reinterpret_cast<uint32_t*>(&h0);
        u.y = *reinterpret_cast<uint32_t*>(&h1);
        out[i] = u;
    }
}

// Transpose-pack weights to half, 64-wide: W[e][k][n] -> Wt[e][k/64][n][64].
__global__ void __launch_bounds__(256)
transpose_pack64_h(const float* __restrict__ W, __half* __restrict__ Wt,
                   int K, int N) {
    const int n  = blockIdx.x * 256 + threadIdx.x;
    const int kt = blockIdx.y;
    const int e  = blockIdx.z;
    const float* src = W + ((size_t)e * K + (size_t)kt * 64) * N + n;
    __half* dst = Wt + (((size_t)e * (K / 64) + kt) * N + n) * 64;
#pragma unroll
    for (int j = 0; j < 64; j += 8) {
        uint4 u;
        __half2 h;
        h = __floats2half2_rn(src[(size_t)(j+0)*N], src[(size_t)(j+1)*N]);
        u.x = *reinterpret_cast<uint32_t*>(&h);
        h = __floats2half2_rn(src[(size_t)(j+2)*N], src[(size_t)(j+3)*N]);
        u.y = *reinterpret_cast<uint32_t*>(&h);
        h = __floats2half2_rn(src[(size_t)(j+4)*N], src[(size_t)(j+5)*N]);
        u.z = *reinterpret_cast<uint32_t*>(&h);
        h = __floats2half2_rn(src[(size_t)(j+6)*N], src[(size_t)(j+7)*N]);
        u.w = *reinterpret_cast<uint32_t*>(&h);
        *reinterpret_cast<uint4*>(dst + j) = u;
    }
}

// ---------------------------------------------------------------------------
// Batched GEMM: Out[e][m][n] = epi( sum_k A[e][m][k]*B[e][k][n] + bias[e][n] )
//   A:  [E][2048][K] row-major half
//   Bt: [E][K/64][ldN][64] K-major packed half
//   CTA 128x128x64, 128 threads (warp grid 2x2 of 64x64), 2 CTAs/SM.
//   GELU=true -> OutT=__half (H); else OutT=float (d_out).
// ---------------------------------------------------------------------------
template <bool GELU, typename OutT>
__global__ void __launch_bounds__(128, 2)
moe_gemm_f16(const __half* __restrict__ A, const __half* __restrict__ Bt,
             const float* __restrict__ bias, OutT* __restrict__ Out,
             int K, int ldN)
{
    extern __shared__ char smem[];
    const int tid  = threadIdx.x;
    const int warp = tid >> 5;
    const int lane = tid & 31;
    const int e  = blockIdx.z;
    const int m0 = blockIdx.x * BM;
    const int n0 = blockIdx.y * BN;
    const int KT = K / BK;

    const __half* Ae  = A  + (size_t)e * EXP_C * K;
    const __half* Bte = Bt + (size_t)e * (K / 64) * ldN * 64 + (size_t)n0 * 64;
    const float*  be  = bias + (size_t)e * ldN;
    OutT*         Oe  = Out  + (size_t)e * EXP_C * ldN;

    const uint32_t sbase = smem_u32(smem);

    const int wm = warp >> 1;    // warp grid 2(M) x 2(N), warp tile 64x64
    const int wn = warp & 1;

    // ---- cp.async geometry: row = tid>>3 (+16*rep), chunk = tid&7 ----
    const int crow   = tid >> 3;              // 0..15
    const int cchunk = tid & 7;               // 8 x 16B per 128B row
    const int cswz   = crow & 7;
    const uint32_t a_dst0 = (uint32_t)(crow * ROW_BYTES + ((cchunk ^ cswz) * 16));

    // running gmem pointers (halves)
    const __half* a_run = Ae  + (size_t)(m0 + crow) * K + cchunk * 8;
    const __half* b_run = Bte + (size_t)crow * 64 + cchunk * 8;

    // ---- ldmatrix geometry ----
    // A frag (m16k16): groups {r0-7,k0-7},{r8-15,k0-7},{r0-7,k8-15},{r8-15,k8-15}
    const int alrow = (lane & 7) + ((lane >> 3) & 1) * 8;
    const int ahi   = lane >> 4;
    // B frag (2 x n8k16): groups {n0-7,k0-7},{n0-7,k8-15},{n8-15,k0-7},{n8-15,k8-15}
    const int blrow = (lane & 7) + ((lane >> 4) & 1) * 8;
    const int bhi   = (lane >> 3) & 1;
    uint32_t afrag[4], bfrag[4];
#pragma unroll
    for (int i = 0; i < 4; ++i) {
        int ra = wm * 64 + i * 16 + alrow;
        afrag[i] = (uint32_t)(ra * ROW_BYTES + ((ahi ^ (ra & 7)) * 16));
        int rb = wn * 64 + i * 16 + blrow;
        bfrag[i] = (uint32_t)(A_BYTES + rb * ROW_BYTES + ((bhi ^ (rb & 7)) * 16));
    }

    float acc[4][8][4];
#pragma unroll
    for (int mt = 0; mt < 4; ++mt)
#pragma unroll
        for (int nt = 0; nt < 8; ++nt)
#pragma unroll
            for (int j = 0; j < 4; ++j) acc[mt][nt][j] = 0.0f;

    auto issue_tile = [&](int stg) {
        const uint32_t st = sbase + (uint32_t)stg * STAGE_BYTES;
#pragma unroll
        for (int rep = 0; rep < 8; ++rep)
            CP_ASYNC_CG(st + a_dst0 + rep * 16u * ROW_BYTES,
                        a_run + (size_t)rep * 16 * K);
#pragma unroll
        for (int rep = 0; rep < 8; ++rep)
            CP_ASYNC_CG(st + A_BYTES + a_dst0 + rep * 16u * ROW_BYTES,
                        b_run + rep * 16 * 64);
        a_run += BK;
        b_run += (size_t)ldN * 64;
    };

#pragma unroll
    for (int t = 0; t < STAGES - 1; ++t) {
        issue_tile(t);
        CP_ASYNC_COMMIT();
    }

    int s  = 0;            // consume stage
    int si = STAGES - 1;   // fill stage (modular counter)
    for (int t = 0; t < KT; ++t) {
        CP_ASYNC_WAIT(STAGES - 2);
        __syncthreads();
        if (t + STAGES - 1 < KT) {
            issue_tile(si);
            if (++si == STAGES) si = 0;
        }
        CP_ASYNC_COMMIT();

        const uint32_t sA = sbase + (uint32_t)s * STAGE_BYTES;
        if (++s == STAGES) s = 0;

        // 4 k16-steps, fragments double-buffered; kk address = base ^ (kk*32)
        uint32_t af[2][4][4], bf[2][4][4];
#pragma unroll
        for (int i = 0; i < 4; ++i) LDSM_X4(af[0][i], sA + afrag[i]);
#pragma unroll
        for (int i = 0; i < 4; ++i) LDSM_X4(bf[0][i], sA + bfrag[i]);

#pragma unroll
        for (int kk = 0; kk < 4; ++kk) {
            const int cur = kk & 1, nxt = cur ^ 1;
            if (kk < 3) {
                const uint32_t x = (uint32_t)(kk + 1) * 32u;
#pragma unroll
                for (int i = 0; i < 4; ++i) LDSM_X4(af[nxt][i], sA + (afrag[i] ^ x));
#pragma unroll
                for (int i = 0; i < 4; ++i) LDSM_X4(bf[nxt][i], sA + (bfrag[i] ^ x));
            }
#pragma unroll
            for (int mt = 0; mt < 4; ++mt)
#pragma unroll
                for (int nt = 0; nt < 8; ++nt)
                    mma_f16(acc[mt][nt], af[cur][mt],
                            bf[cur][nt >> 1][(nt & 1) * 2],
                            bf[cur][nt >> 1][(nt & 1) * 2 + 1]);
        }
    }

    // ---- epilogue: direct reg -> gmem, fused bias (+GELU) ----
    const int g     = lane >> 2;
    const int cpair = (lane & 3) * 2;
    float2 bv[8];
#pragma unroll
    for (int nt = 0; nt < 8; ++nt)
        bv[nt] = *reinterpret_cast<const float2*>(be + n0 + wn * 64 + nt * 8 + cpair);

#pragma unroll
    for (int mt = 0; mt < 4; ++mt) {
#pragma unroll
        for (int h = 0; h < 2; ++h) {
            const int grow = m0 + wm * 64 + mt * 16 + g + h * 8;
            OutT* op = Oe + (size_t)grow * ldN + n0 + wn * 64 + cpair;
#pragma unroll
            for (int nt = 0; nt < 8; ++nt) {
                float x0 = acc[mt][nt][h * 2]     + bv[nt].x;
                float x1 = acc[mt][nt][h * 2 + 1] + bv[nt].y;
                if (GELU) {
                    // H feeds GEMM2 as fp16 A operand
                    __half2 hv = __floats2half2_rn(gelu_tanh(x0), gelu_tanh(x1));
                    *reinterpret_cast<__half2*>((__half*)op + nt * 8) = hv;
                } else {
                    *reinterpret_cast<float2*>((float*)op + nt * 8) =
                        make_float2(x0, x1);
                }
            }
        }
    }
}

// ---------------------------------------------------------------------------
// kernel_launch
// ---------------------------------------------------------------------------
extern "C" void kernel_launch(void* const* d_in, const int* in_sizes, int n_in,
                              void* d_out, int out_size) {
    (void)in_sizes; (void)n_in; (void)out_size;
    const float* inputs = (const float*)d_in[0];
    const float* w1     = (const float*)d_in[1];
    const float* b1     = (const float*)d_in[2];
    const float* w2     = (const float*)d_in[3];
    const float* b2     = (const float*)d_in[4];
    float* out = (float*)d_out;

    void *hp, *xp, *w1p, *w2p;
    cudaGetSymbolAddress(&hp,  g_H);
    cudaGetSymbolAddress(&xp,  g_Xh);
    cudaGetSymbolAddress(&w1p, g_W1h);
    cudaGetSymbolAddress(&w2p, g_W2h);
    __half* H   = (__half*)hp;
    __half* Xh  = (__half*)xp;
    __half* W1h = (__half*)w1p;
    __half* W2h = (__half*)w2p;

    const size_t nX = (size_t)EXP_E * EXP_C * EXP_D / 4;
    to_half_pass<<<2048, 256>>>((const float4*)inputs, (uint2*)Xh, nX);

    dim3 t1(EXP_F / 256, EXP_D / 64, EXP_E);   // W1: K=D, N=F
    transpose_pack64_h<<<t1, 256>>>(w1, W1h, EXP_D, EXP_F);
    dim3 t2(EXP_D / 256, EXP_F / 64, EXP_E);   // W2: K=F, N=D
    transpose_pack64_h<<<t2, 256>>>(w2, W2h, EXP_F, EXP_D);

    cudaFuncSetAttribute((const void*)moe_gemm_f16<true, __half>,
                         cudaFuncAttributeMaxDynamicSharedMemorySize, SMEM_BYTES);
    cudaFuncSetAttribute((const void*)moe_gemm_f16<false, float>,
                         cudaFuncAttributeMaxDynamicSharedMemorySize, SMEM_BYTES);

    dim3 g1(EXP_C / BM, EXP_F / BN, EXP_E);    // (16, 64, 8)
    moe_gemm_f16<true, __half><<<g1, 128, SMEM_BYTES>>>(Xh, W1h, b1, H, EXP_D, EXP_F);

    dim3 g2(EXP_C / BM, EXP_D / BN, EXP_E);    // (16, 16, 8)
    moe_gemm_f16<false, float><<<g2, 128, SMEM_BYTES>>>(H, W2h, b2, out, EXP_F, EXP_D);
}